// round 2
// baseline (speedup 1.0000x reference)
#include <cuda_runtime.h>
#include <cuda_bf16.h>
#include <math.h>

// ---------------- problem constants ----------------
#define N_NODES 10000
#define N_EDGES 160000
#define IN_DIM  256
#define HID_DIM 512
#define OUT_DIM 256

// ---------------- device scratch (no allocs allowed) ----------------
__device__ float g_bufA[N_NODES * HID_DIM];   // 20.48 MB
__device__ float g_bufB[N_NODES * HID_DIM];   // 20.48 MB
__device__ float g_dinv[N_NODES];
__device__ int   g_cnt[N_NODES];
__device__ int   g_rowptr[N_NODES + 1];
__device__ int   g_cursor[N_NODES];
__device__ int   g_colsrc[N_EDGES];

// ---------------- preprocessing kernels ----------------
__global__ void zero_cnt_kernel(int* cnt, int n) {
    int i = blockIdx.x * blockDim.x + threadIdx.x;
    if (i < n) cnt[i] = 0;
}

// edge_index is int32 (JAX demotes int64 -> int32 without x64).
__global__ void count_edges_kernel(const int* __restrict__ ei, int* cnt, int E) {
    int e = blockIdx.x * blockDim.x + threadIdx.x;
    if (e < E) {
        int d = ei[E + e];   // dst row
        if (d >= 0 && d < N_NODES) atomicAdd(&cnt[d], 1);
    }
}

// single-block exclusive scan over counts -> rowptr, cursor; also dinv = rsqrt(cnt+1)
__global__ void scan_kernel(const int* __restrict__ cnt, int* rowptr, int* cursor,
                            float* dinv, int n) {
    __shared__ int ssum[1024];
    int tid = threadIdx.x;
    const int CH = (n + 1023) / 1024;
    int base = tid * CH;
    int local = 0;
    for (int i = 0; i < CH; i++) {
        int idx = base + i;
        if (idx < n) local += cnt[idx];
    }
    ssum[tid] = local;
    __syncthreads();
    // inclusive Hillis-Steele scan over thread sums
    for (int off = 1; off < 1024; off <<= 1) {
        int v = ssum[tid];
        int add = (tid >= off) ? ssum[tid - off] : 0;
        __syncthreads();
        ssum[tid] = v + add;
        __syncthreads();
    }
    int run = (tid > 0) ? ssum[tid - 1] : 0;  // exclusive prefix for this chunk
    for (int i = 0; i < CH; i++) {
        int idx = base + i;
        if (idx < n) {
            rowptr[idx] = run;
            cursor[idx] = run;
            int c = cnt[idx];
            run += c;
            dinv[idx] = rsqrtf((float)c + 1.0f);
        }
    }
    if (tid == 1023) rowptr[n] = run;  // == total edge count
}

__global__ void fill_csr_kernel(const int* __restrict__ ei, int* cursor,
                                int* colsrc, int E) {
    int e = blockIdx.x * blockDim.x + threadIdx.x;
    if (e < E) {
        int s = ei[e];         // src
        int d = ei[E + e];     // dst
        if (d >= 0 && d < N_NODES) {
            int p = atomicAdd(&cursor[d], 1);
            colsrc[p] = s;
        }
    }
}

// ---------------- GEMM: C[r][c] = dinv[r] * sum_k A[r][k] * B[k][c] ----------------
// A: Mm x Kk row-major, B: Kk x Nn row-major, C: Mm x Nn.
// 128x128 tile, BK=8, 256 threads, 8x8 per thread. Nn % 128 == 0, Kk % 8 == 0 assumed.
__global__ __launch_bounds__(256) void sgemm_scaled_kernel(
    const float* __restrict__ A, const float* __restrict__ B,
    const float* __restrict__ dinv, float* __restrict__ C,
    int Mm, int Nn, int Kk)
{
    const int BM = 128, BN = 128, BK = 8, TM = 8, TN = 8;
    __shared__ __align__(16) float As[BK][BM];   // transposed A tile
    __shared__ __align__(16) float Bs[BK][BN];

    int tid  = threadIdx.x;
    int row0 = blockIdx.y * BM;
    int col0 = blockIdx.x * BN;

    int tr = (tid / 16) * TM;   // 0..120
    int tc = (tid % 16) * TN;   // 0..120

    float acc[TM][TN];
#pragma unroll
    for (int m = 0; m < TM; m++)
#pragma unroll
        for (int n = 0; n < TN; n++) acc[m][n] = 0.0f;

    // A tile load mapping: 128 rows x 8 cols (float4 each, 2 threads/row)
    int a_row = tid >> 1;
    int a_col = (tid & 1) * 4;
    int gRow  = row0 + a_row;
    // B tile load mapping: 8 rows x 128 cols (float4 each, 32 threads/row)
    int b_row = tid >> 5;
    int b_col = (tid & 31) * 4;

    for (int k0 = 0; k0 < Kk; k0 += BK) {
        float4 av;
        if (gRow < Mm)
            av = *(const float4*)(A + (size_t)gRow * Kk + k0 + a_col);
        else
            av = make_float4(0.f, 0.f, 0.f, 0.f);
        As[a_col + 0][a_row] = av.x;
        As[a_col + 1][a_row] = av.y;
        As[a_col + 2][a_row] = av.z;
        As[a_col + 3][a_row] = av.w;

        float4 bv = *(const float4*)(B + (size_t)(k0 + b_row) * Nn + col0 + b_col);
        *(float4*)&Bs[b_row][b_col] = bv;

        __syncthreads();

#pragma unroll
        for (int k = 0; k < BK; k++) {
            float4 a0 = *(const float4*)&As[k][tr];
            float4 a1 = *(const float4*)&As[k][tr + 4];
            float4 b0 = *(const float4*)&Bs[k][tc];
            float4 b1 = *(const float4*)&Bs[k][tc + 4];
            float ar[TM] = {a0.x, a0.y, a0.z, a0.w, a1.x, a1.y, a1.z, a1.w};
            float br[TN] = {b0.x, b0.y, b0.z, b0.w, b1.x, b1.y, b1.z, b1.w};
#pragma unroll
            for (int m = 0; m < TM; m++)
#pragma unroll
                for (int n = 0; n < TN; n++)
                    acc[m][n] = fmaf(ar[m], br[n], acc[m][n]);
        }
        __syncthreads();
    }

    // epilogue: scale each row by dinv[row]
#pragma unroll
    for (int m = 0; m < TM; m++) {
        int r = row0 + tr + m;
        if (r < Mm) {
            float s = dinv[r];
            float4 o0, o1;
            o0.x = acc[m][0] * s; o0.y = acc[m][1] * s;
            o0.z = acc[m][2] * s; o0.w = acc[m][3] * s;
            o1.x = acc[m][4] * s; o1.y = acc[m][5] * s;
            o1.z = acc[m][6] * s; o1.w = acc[m][7] * s;
            float* cp = C + (size_t)r * Nn + col0 + tc;
            *(float4*)(cp)     = o0;
            *(float4*)(cp + 4) = o1;
        }
    }
}

// ---------------- aggregation: out[i] = act( dinv[i]*(G[i] + sum_e G[src_e]) + b ) ----------------
// One block per node, F4 threads, one float4 of features per thread.
__global__ void agg_kernel(const float* __restrict__ G,
                           const float* __restrict__ bias,
                           const float* __restrict__ dinv,
                           const int* __restrict__ rowptr,
                           const int* __restrict__ colsrc,
                           float* __restrict__ out,
                           int F4, int apply_tanh)
{
    int i = blockIdx.x;
    int t = threadIdx.x;
    const float4* G4 = (const float4*)G;

    float4 acc = __ldg(&G4[(size_t)i * F4 + t]);   // self-loop term

    int e   = rowptr[i];
    int end = rowptr[i + 1];
    for (; e + 4 <= end; e += 4) {
        int s0 = __ldg(&colsrc[e + 0]);
        int s1 = __ldg(&colsrc[e + 1]);
        int s2 = __ldg(&colsrc[e + 2]);
        int s3 = __ldg(&colsrc[e + 3]);
        float4 v0 = __ldg(&G4[(size_t)s0 * F4 + t]);
        float4 v1 = __ldg(&G4[(size_t)s1 * F4 + t]);
        float4 v2 = __ldg(&G4[(size_t)s2 * F4 + t]);
        float4 v3 = __ldg(&G4[(size_t)s3 * F4 + t]);
        acc.x += v0.x + v1.x + v2.x + v3.x;
        acc.y += v0.y + v1.y + v2.y + v3.y;
        acc.z += v0.z + v1.z + v2.z + v3.z;
        acc.w += v0.w + v1.w + v2.w + v3.w;
    }
    for (; e < end; ++e) {
        int s = __ldg(&colsrc[e]);
        float4 v = __ldg(&G4[(size_t)s * F4 + t]);
        acc.x += v.x; acc.y += v.y; acc.z += v.z; acc.w += v.w;
    }

    float di = dinv[i];
    float4 bb = ((const float4*)bias)[t];
    float4 r;
    r.x = fmaf(acc.x, di, bb.x);
    r.y = fmaf(acc.y, di, bb.y);
    r.z = fmaf(acc.z, di, bb.z);
    r.w = fmaf(acc.w, di, bb.w);
    if (apply_tanh) {
        r.x = tanhf(r.x); r.y = tanhf(r.y);
        r.z = tanhf(r.z); r.w = tanhf(r.w);
    }
    ((float4*)out)[(size_t)i * F4 + t] = r;
}

// ---------------- launch ----------------
extern "C" void kernel_launch(void* const* d_in, const int* in_sizes, int n_in,
                              void* d_out, int out_size) {
    const float* x  = (const float*)d_in[0];
    const float* W1 = (const float*)d_in[1];
    const float* b1 = (const float*)d_in[2];
    const float* W2 = (const float*)d_in[3];
    const float* b2 = (const float*)d_in[4];
    const float* W3 = (const float*)d_in[5];
    const float* b3 = (const float*)d_in[6];
    const int*   ei = (const int*)d_in[7];    // int32 edge_index [2, E]
    float* out = (float*)d_out;

    const int N = N_NODES;
    const int E = in_sizes[7] / 2;

    float *bufA, *bufB, *dinv;
    int *cnt, *rowptr, *cursor, *colsrc;
    cudaGetSymbolAddress((void**)&bufA,   g_bufA);
    cudaGetSymbolAddress((void**)&bufB,   g_bufB);
    cudaGetSymbolAddress((void**)&dinv,   g_dinv);
    cudaGetSymbolAddress((void**)&cnt,    g_cnt);
    cudaGetSymbolAddress((void**)&rowptr, g_rowptr);
    cudaGetSymbolAddress((void**)&cursor, g_cursor);
    cudaGetSymbolAddress((void**)&colsrc, g_colsrc);

    // --- preprocessing: degrees + CSR by dst ---
    zero_cnt_kernel<<<(N + 255) / 256, 256>>>(cnt, N);
    count_edges_kernel<<<(E + 255) / 256, 256>>>(ei, cnt, E);
    scan_kernel<<<1, 1024>>>(cnt, rowptr, cursor, dinv, N);
    fill_csr_kernel<<<(E + 255) / 256, 256>>>(ei, cursor, colsrc, E);

    // --- layer 1: H1 = (x @ W1) * dinv -> bufA ; A1 = agg+tanh -> bufB ---
    {
        dim3 grid(HID_DIM / 128, (N + 127) / 128);
        sgemm_scaled_kernel<<<grid, 256>>>(x, W1, dinv, bufA, N, HID_DIM, IN_DIM);
        agg_kernel<<<N, HID_DIM / 4>>>(bufA, b1, dinv, rowptr, colsrc, bufB, HID_DIM / 4, 1);
    }
    // --- layer 2: H2 = (A1 @ W2) * dinv -> bufA ; A2 = agg+tanh -> bufB ---
    {
        dim3 grid(HID_DIM / 128, (N + 127) / 128);
        sgemm_scaled_kernel<<<grid, 256>>>(bufB, W2, dinv, bufA, N, HID_DIM, HID_DIM);
        agg_kernel<<<N, HID_DIM / 4>>>(bufA, b2, dinv, rowptr, colsrc, bufB, HID_DIM / 4, 1);
    }
    // --- layer 3: H3 = (A2 @ W3) * dinv -> bufA ; out = agg (no act) ---
    {
        dim3 grid(OUT_DIM / 128, (N + 127) / 128);
        sgemm_scaled_kernel<<<grid, 256>>>(bufB, W3, dinv, bufA, N, OUT_DIM, HID_DIM);
        agg_kernel<<<N, OUT_DIM / 4>>>(bufA, b3, dinv, rowptr, colsrc, out, OUT_DIM / 4, 0);
    }
}

// round 4
// speedup vs baseline: 1.8302x; 1.8302x over previous
#include <cuda_runtime.h>
#include <cuda_bf16.h>
#include <math.h>
#include <stdint.h>

// ---------------- problem constants ----------------
#define N_NODES 10000
#define N_EDGES 160000
#define IN_DIM  256
#define HID_DIM 512
#define OUT_DIM 256

// ---------------- device scratch (no allocs allowed) ----------------
__device__ float g_bufA[N_NODES * HID_DIM];          // GEMM output (scaled)
__device__ float g_bufB[N_NODES * HID_DIM];          // aggregated activations
__device__ __nv_bfloat16 g_hiA[N_NODES * HID_DIM];   // activation hi split
__device__ __nv_bfloat16 g_loA[N_NODES * HID_DIM];   // activation lo split
__device__ __nv_bfloat16 g_WtHi[HID_DIM * HID_DIM];  // W^T hi split
__device__ __nv_bfloat16 g_WtLo[HID_DIM * HID_DIM];  // W^T lo split
__device__ float g_dinv[N_NODES];
__device__ int   g_cnt[N_NODES];
__device__ int   g_rowptr[N_NODES + 1];
__device__ int   g_cursor[N_NODES];
__device__ int   g_colsrc[N_EDGES];

// ---------------- preprocessing kernels ----------------
__global__ void zero_cnt_kernel(int* cnt, int n) {
    int i = blockIdx.x * blockDim.x + threadIdx.x;
    if (i < n) cnt[i] = 0;
}

__global__ void count_edges_kernel(const int* __restrict__ ei, int* cnt, int E) {
    int e = blockIdx.x * blockDim.x + threadIdx.x;
    if (e < E) {
        int d = ei[E + e];
        if (d >= 0 && d < N_NODES) atomicAdd(&cnt[d], 1);
    }
}

__global__ void scan_kernel(const int* __restrict__ cnt, int* rowptr, int* cursor,
                            float* dinv, int n) {
    __shared__ int ssum[1024];
    int tid = threadIdx.x;
    const int CH = (n + 1023) / 1024;
    int base = tid * CH;
    int local = 0;
    for (int i = 0; i < CH; i++) {
        int idx = base + i;
        if (idx < n) local += cnt[idx];
    }
    ssum[tid] = local;
    __syncthreads();
    for (int off = 1; off < 1024; off <<= 1) {
        int v = ssum[tid];
        int add = (tid >= off) ? ssum[tid - off] : 0;
        __syncthreads();
        ssum[tid] = v + add;
        __syncthreads();
    }
    int run = (tid > 0) ? ssum[tid - 1] : 0;
    for (int i = 0; i < CH; i++) {
        int idx = base + i;
        if (idx < n) {
            rowptr[idx] = run;
            cursor[idx] = run;
            int c = cnt[idx];
            run += c;
            dinv[idx] = rsqrtf((float)c + 1.0f);
        }
    }
    if (tid == 1023) rowptr[n] = run;
}

__global__ void fill_csr_kernel(const int* __restrict__ ei, int* cursor,
                                int* colsrc, int E) {
    int e = blockIdx.x * blockDim.x + threadIdx.x;
    if (e < E) {
        int s = ei[e];
        int d = ei[E + e];
        if (d >= 0 && d < N_NODES) {
            int p = atomicAdd(&cursor[d], 1);
            colsrc[p] = s;
        }
    }
}

// ---------------- fp32 -> bf16 hi/lo split (activations, flat) ----------------
__global__ void convert_split_kernel(const float* __restrict__ X,
                                     uint32_t* __restrict__ hi2,
                                     uint32_t* __restrict__ lo2, int total4) {
    int i = blockIdx.x * blockDim.x + threadIdx.x;
    if (i >= total4) return;
    float4 v = ((const float4*)X)[i];
    __nv_bfloat16 h0 = __float2bfloat16(v.x);
    __nv_bfloat16 h1 = __float2bfloat16(v.y);
    __nv_bfloat16 h2 = __float2bfloat16(v.z);
    __nv_bfloat16 h3 = __float2bfloat16(v.w);
    __nv_bfloat16 l0 = __float2bfloat16(v.x - __bfloat162float(h0));
    __nv_bfloat16 l1 = __float2bfloat16(v.y - __bfloat162float(h1));
    __nv_bfloat16 l2 = __float2bfloat16(v.z - __bfloat162float(h2));
    __nv_bfloat16 l3 = __float2bfloat16(v.w - __bfloat162float(h3));
    hi2[2 * i]     = (uint32_t)__bfloat16_as_ushort(h0) | ((uint32_t)__bfloat16_as_ushort(h1) << 16);
    hi2[2 * i + 1] = (uint32_t)__bfloat16_as_ushort(h2) | ((uint32_t)__bfloat16_as_ushort(h3) << 16);
    lo2[2 * i]     = (uint32_t)__bfloat16_as_ushort(l0) | ((uint32_t)__bfloat16_as_ushort(l1) << 16);
    lo2[2 * i + 1] = (uint32_t)__bfloat16_as_ushort(l2) | ((uint32_t)__bfloat16_as_ushort(l3) << 16);
}

// ---------------- W [K,N] fp32 -> W^T [N,K] bf16 hi/lo ----------------
__global__ void convert_wt_kernel(const float* __restrict__ W,
                                  __nv_bfloat16* __restrict__ wtHi,
                                  __nv_bfloat16* __restrict__ wtLo,
                                  int Kk, int Nn) {
    int i = blockIdx.x * blockDim.x + threadIdx.x;
    if (i >= Kk * Nn) return;
    int k = i / Nn, n = i % Nn;
    float v = W[i];
    __nv_bfloat16 h = __float2bfloat16(v);
    wtHi[(size_t)n * Kk + k] = h;
    wtLo[(size_t)n * Kk + k] = __float2bfloat16(v - __bfloat162float(h));
}

// ---------------- mma.sync bf16 GEMM ----------------
// C[r][c] = dinv[r] * sum_k A[r][k] * Wt[c][k], fp32 accum, bf16 hi/lo 3-mma split.
// CTA tile 128x128; 8 warps (2M x 4N), warp tile 64x32; BK=32 double-buffered cp.async.
#define RSU 20                         // smem row stride in u32 (16 data + 4 pad), 80B rows
#define TILE_U32 (128 * RSU)           // 2560 u32 per tile
#define GEMM_SMEM (2 * 4 * TILE_U32 * 4)   // 81920 bytes

__device__ __forceinline__ void cp16(uint32_t dst, const void* src, bool pred) {
    int sz = pred ? 16 : 0;
    asm volatile("cp.async.cg.shared.global [%0], [%1], 16, %2;"
                 :: "r"(dst), "l"(src), "r"(sz) : "memory");
}
__device__ __forceinline__ void mma_bf16(float c[4], const uint32_t a[4], const uint32_t b[2]) {
    asm volatile(
        "mma.sync.aligned.m16n8k16.row.col.f32.bf16.bf16.f32 "
        "{%0,%1,%2,%3}, {%4,%5,%6,%7}, {%8,%9}, {%0,%1,%2,%3};"
        : "+f"(c[0]), "+f"(c[1]), "+f"(c[2]), "+f"(c[3])
        : "r"(a[0]), "r"(a[1]), "r"(a[2]), "r"(a[3]), "r"(b[0]), "r"(b[1]));
}
__device__ __forceinline__ uint32_t smem_u32p(const void* p) {
    uint32_t a;
    asm("{ .reg .u64 t; cvta.to.shared.u64 t, %1; cvt.u32.u64 %0, t; }" : "=r"(a) : "l"(p));
    return a;
}

__global__ __launch_bounds__(256, 1) void gemm_mma_kernel(
    const uint32_t* __restrict__ Ahi2, const uint32_t* __restrict__ Alo2,
    const uint32_t* __restrict__ Bhi2, const uint32_t* __restrict__ Blo2,
    const float* __restrict__ dinv, float* __restrict__ C,
    int Mm, int Nn, int Kk)
{
    extern __shared__ __align__(16) uint32_t sm[];
    const uint32_t sb = smem_u32p(sm);

    const int tid = threadIdx.x;
    const int wid = tid >> 5;
    const int lid = tid & 31;
    const int g = lid >> 2;       // groupID
    const int t = lid & 3;        // threadID in group
    const int row0 = blockIdx.y * 128;
    const int col0 = blockIdx.x * 128;
    const int m0 = (wid & 1) * 64;    // warp M offset
    const int n0 = (wid >> 1) * 32;   // warp N offset
    const int Ku = Kk >> 1;           // K in u32 units

    float acc[4][4][4];
#pragma unroll
    for (int mt = 0; mt < 4; mt++)
#pragma unroll
        for (int nt = 0; nt < 4; nt++)
#pragma unroll
            for (int i = 0; i < 4; i++) acc[mt][nt][i] = 0.0f;

    // async loader: one K-tile (32 bf16 = 16 u32 per row) x 4 tiles into buffer `buf`
    auto load_tiles = [&](int buf, int kt) {
        const int k0u = kt * 16;
#pragma unroll
        for (int half = 0; half < 2; half++) {
            int c = tid + half * 256;     // chunk id 0..511
            int row = c >> 2;
            int cq = (c & 3) * 4;         // u32 offset in row
            // A hi/lo
            int gr = row0 + row;
            bool inb = gr < Mm;
            int gra = inb ? gr : (Mm - 1);
            const uint32_t* sA = Ahi2 + (size_t)gra * Ku + k0u + cq;
            const uint32_t* sL = Alo2 + (size_t)gra * Ku + k0u + cq;
            uint32_t dst0 = sb + (uint32_t)(((buf * 4 + 0) * TILE_U32 + row * RSU + cq) * 4);
            uint32_t dst1 = sb + (uint32_t)(((buf * 4 + 1) * TILE_U32 + row * RSU + cq) * 4);
            cp16(dst0, sA, inb);
            cp16(dst1, sL, inb);
            // B hi/lo (rows are N-dim, always in-bounds)
            int gn = col0 + row;
            const uint32_t* sBh = Bhi2 + (size_t)gn * Ku + k0u + cq;
            const uint32_t* sBl = Blo2 + (size_t)gn * Ku + k0u + cq;
            uint32_t dst2 = sb + (uint32_t)(((buf * 4 + 2) * TILE_U32 + row * RSU + cq) * 4);
            uint32_t dst3 = sb + (uint32_t)(((buf * 4 + 3) * TILE_U32 + row * RSU + cq) * 4);
            cp16(dst2, sBh, true);
            cp16(dst3, sBl, true);
        }
        asm volatile("cp.async.commit_group;" ::: "memory");
    };

    const int nkt = Kk / 32;
    load_tiles(0, 0);

    for (int kt = 0; kt < nkt; kt++) {
        int buf = kt & 1;
        if (kt + 1 < nkt) {
            load_tiles(buf ^ 1, kt + 1);
            asm volatile("cp.async.wait_group 1;" ::: "memory");
        } else {
            asm volatile("cp.async.wait_group 0;" ::: "memory");
        }
        __syncthreads();

        const uint32_t* sAh = sm + (buf * 4 + 0) * TILE_U32;
        const uint32_t* sAl = sm + (buf * 4 + 1) * TILE_U32;
        const uint32_t* sBh = sm + (buf * 4 + 2) * TILE_U32;
        const uint32_t* sBl = sm + (buf * 4 + 3) * TILE_U32;

#pragma unroll
        for (int ks = 0; ks < 2; ks++) {
            const int kb = ks * 8;
            uint32_t ah[4][4], al[4][4], bh[4][2], bl[4][2];
#pragma unroll
            for (int mt = 0; mt < 4; mt++) {
                int rm = m0 + mt * 16 + g;
                const uint32_t* p0 = sAh + rm * RSU + kb + t;
                const uint32_t* p1 = sAh + (rm + 8) * RSU + kb + t;
                ah[mt][0] = p0[0]; ah[mt][2] = p0[4];
                ah[mt][1] = p1[0]; ah[mt][3] = p1[4];
                const uint32_t* q0 = sAl + rm * RSU + kb + t;
                const uint32_t* q1 = sAl + (rm + 8) * RSU + kb + t;
                al[mt][0] = q0[0]; al[mt][2] = q0[4];
                al[mt][1] = q1[0]; al[mt][3] = q1[4];
            }
#pragma unroll
            for (int nt = 0; nt < 4; nt++) {
                int rn = n0 + nt * 8 + g;
                const uint32_t* pb = sBh + rn * RSU + kb + t;
                const uint32_t* qb = sBl + rn * RSU + kb + t;
                bh[nt][0] = pb[0]; bh[nt][1] = pb[4];
                bl[nt][0] = qb[0]; bl[nt][1] = qb[4];
            }
#pragma unroll
            for (int mt = 0; mt < 4; mt++)
#pragma unroll
                for (int nt = 0; nt < 4; nt++) {
                    mma_bf16(acc[mt][nt], ah[mt], bh[nt]);   // hi*hi
                    mma_bf16(acc[mt][nt], al[mt], bh[nt]);   // lo*hi
                    mma_bf16(acc[mt][nt], ah[mt], bl[nt]);   // hi*lo
                }
        }
        __syncthreads();
    }

    // ---- epilogue: direct register -> gmem with dinv row scale ----
#pragma unroll
    for (int mt = 0; mt < 4; mt++) {
        int r0 = row0 + m0 + mt * 16 + g;
        int r1 = r0 + 8;
        float s0 = (r0 < Mm) ? dinv[r0] : 0.0f;
        float s1 = (r1 < Mm) ? dinv[r1] : 0.0f;
#pragma unroll
        for (int nt = 0; nt < 4; nt++) {
            int cn = col0 + n0 + nt * 8 + t * 2;
            if (r0 < Mm) {
                float2 v0 = make_float2(acc[mt][nt][0] * s0, acc[mt][nt][1] * s0);
                *(float2*)(C + (size_t)r0 * Nn + cn) = v0;
            }
            if (r1 < Mm) {
                float2 v1 = make_float2(acc[mt][nt][2] * s1, acc[mt][nt][3] * s1);
                *(float2*)(C + (size_t)r1 * Nn + cn) = v1;
            }
        }
    }
}

// ---------------- aggregation: out[i] = act( dinv[i]*(G[i] + sum_e G[src_e]) + b ) ----------------
__global__ void agg_kernel(const float* __restrict__ G,
                           const float* __restrict__ bias,
                           const float* __restrict__ dinv,
                           const int* __restrict__ rowptr,
                           const int* __restrict__ colsrc,
                           float* __restrict__ out,
                           int F4, int apply_tanh)
{
    int i = blockIdx.x;
    int t = threadIdx.x;
    const float4* G4 = (const float4*)G;

    float4 acc = __ldg(&G4[(size_t)i * F4 + t]);

    int e   = rowptr[i];
    int end = rowptr[i + 1];
    for (; e + 4 <= end; e += 4) {
        int s0 = __ldg(&colsrc[e + 0]);
        int s1 = __ldg(&colsrc[e + 1]);
        int s2 = __ldg(&colsrc[e + 2]);
        int s3 = __ldg(&colsrc[e + 3]);
        float4 v0 = __ldg(&G4[(size_t)s0 * F4 + t]);
        float4 v1 = __ldg(&G4[(size_t)s1 * F4 + t]);
        float4 v2 = __ldg(&G4[(size_t)s2 * F4 + t]);
        float4 v3 = __ldg(&G4[(size_t)s3 * F4 + t]);
        acc.x += v0.x + v1.x + v2.x + v3.x;
        acc.y += v0.y + v1.y + v2.y + v3.y;
        acc.z += v0.z + v1.z + v2.z + v3.z;
        acc.w += v0.w + v1.w + v2.w + v3.w;
    }
    for (; e < end; ++e) {
        int s = __ldg(&colsrc[e]);
        float4 v = __ldg(&G4[(size_t)s * F4 + t]);
        acc.x += v.x; acc.y += v.y; acc.z += v.z; acc.w += v.w;
    }

    float di = dinv[i];
    float4 bb = ((const float4*)bias)[t];
    float4 r;
    r.x = fmaf(acc.x, di, bb.x);
    r.y = fmaf(acc.y, di, bb.y);
    r.z = fmaf(acc.z, di, bb.z);
    r.w = fmaf(acc.w, di, bb.w);
    if (apply_tanh) {
        r.x = tanhf(r.x); r.y = tanhf(r.y);
        r.z = tanhf(r.z); r.w = tanhf(r.w);
    }
    ((float4*)out)[(size_t)i * F4 + t] = r;
}

// ---------------- launch ----------------
extern "C" void kernel_launch(void* const* d_in, const int* in_sizes, int n_in,
                              void* d_out, int out_size) {
    const float* x  = (const float*)d_in[0];
    const float* W1 = (const float*)d_in[1];
    const float* b1 = (const float*)d_in[2];
    const float* W2 = (const float*)d_in[3];
    const float* b2 = (const float*)d_in[4];
    const float* W3 = (const float*)d_in[5];
    const float* b3 = (const float*)d_in[6];
    const int*   ei = (const int*)d_in[7];    // int32 edge_index [2, E]
    float* out = (float*)d_out;

    const int N = N_NODES;
    const int E = in_sizes[7] / 2;

    float *bufA, *bufB, *dinv;
    int *cnt, *rowptr, *cursor, *colsrc;
    __nv_bfloat16 *hiA, *loA, *wtHi, *wtLo;
    cudaGetSymbolAddress((void**)&bufA,   g_bufA);
    cudaGetSymbolAddress((void**)&bufB,   g_bufB);
    cudaGetSymbolAddress((void**)&dinv,   g_dinv);
    cudaGetSymbolAddress((void**)&cnt,    g_cnt);
    cudaGetSymbolAddress((void**)&rowptr, g_rowptr);
    cudaGetSymbolAddress((void**)&cursor, g_cursor);
    cudaGetSymbolAddress((void**)&colsrc, g_colsrc);
    cudaGetSymbolAddress((void**)&hiA,    g_hiA);
    cudaGetSymbolAddress((void**)&loA,    g_loA);
    cudaGetSymbolAddress((void**)&wtHi,   g_WtHi);
    cudaGetSymbolAddress((void**)&wtLo,   g_WtLo);

    static bool attr_set = false;
    if (!attr_set) {
        cudaFuncSetAttribute(gemm_mma_kernel, cudaFuncAttributeMaxDynamicSharedMemorySize, GEMM_SMEM);
        attr_set = true;
    }

    // --- preprocessing: degrees + CSR by dst ---
    zero_cnt_kernel<<<(N + 255) / 256, 256>>>(cnt, N);
    count_edges_kernel<<<(E + 255) / 256, 256>>>(ei, cnt, E);
    scan_kernel<<<1, 1024>>>(cnt, rowptr, cursor, dinv, N);
    fill_csr_kernel<<<(E + 255) / 256, 256>>>(ei, cursor, colsrc, E);

    const int MT = (N + 127) / 128;  // 79 row tiles

    // --- layer 1: x[N,256] @ W1[256,512] ---
    convert_split_kernel<<<(N * IN_DIM / 4 + 255) / 256, 256>>>(x, (uint32_t*)hiA, (uint32_t*)loA, N * IN_DIM / 4);
    convert_wt_kernel<<<(IN_DIM * HID_DIM + 255) / 256, 256>>>(W1, wtHi, wtLo, IN_DIM, HID_DIM);
    {
        dim3 grid(HID_DIM / 128, MT);
        gemm_mma_kernel<<<grid, 256, GEMM_SMEM>>>((uint32_t*)hiA, (uint32_t*)loA,
                                                  (uint32_t*)wtHi, (uint32_t*)wtLo,
                                                  dinv, bufA, N, HID_DIM, IN_DIM);
        agg_kernel<<<N, HID_DIM / 4>>>(bufA, b1, dinv, rowptr, colsrc, bufB, HID_DIM / 4, 1);
    }
    // --- layer 2: bufB[N,512] @ W2[512,512] ---
    convert_split_kernel<<<(N * HID_DIM / 4 + 255) / 256, 256>>>(bufB, (uint32_t*)hiA, (uint32_t*)loA, N * HID_DIM / 4);
    convert_wt_kernel<<<(HID_DIM * HID_DIM + 255) / 256, 256>>>(W2, wtHi, wtLo, HID_DIM, HID_DIM);
    {
        dim3 grid(HID_DIM / 128, MT);
        gemm_mma_kernel<<<grid, 256, GEMM_SMEM>>>((uint32_t*)hiA, (uint32_t*)loA,
                                                  (uint32_t*)wtHi, (uint32_t*)wtLo,
                                                  dinv, bufA, N, HID_DIM, HID_DIM);
        agg_kernel<<<N, HID_DIM / 4>>>(bufA, b2, dinv, rowptr, colsrc, bufB, HID_DIM / 4, 1);
    }
    // --- layer 3: bufB[N,512] @ W3[512,256] ---
    convert_split_kernel<<<(N * HID_DIM / 4 + 255) / 256, 256>>>(bufB, (uint32_t*)hiA, (uint32_t*)loA, N * HID_DIM / 4);
    convert_wt_kernel<<<(HID_DIM * OUT_DIM + 255) / 256, 256>>>(W3, wtHi, wtLo, HID_DIM, OUT_DIM);
    {
        dim3 grid(OUT_DIM / 128, MT);
        gemm_mma_kernel<<<grid, 256, GEMM_SMEM>>>((uint32_t*)hiA, (uint32_t*)loA,
                                                  (uint32_t*)wtHi, (uint32_t*)wtLo,
                                                  dinv, bufA, N, OUT_DIM, HID_DIM);
        agg_kernel<<<N, OUT_DIM / 4>>>(bufA, b3, dinv, rowptr, colsrc, out, OUT_DIM / 4, 0);
    }
}

// round 5
// speedup vs baseline: 1.9319x; 1.0556x over previous
#include <cuda_runtime.h>
#include <cuda_bf16.h>
#include <math.h>
#include <stdint.h>

// ---------------- problem constants ----------------
#define N_NODES 10000
#define N_EDGES 160000
#define IN_DIM  256
#define HID_DIM 512
#define OUT_DIM 256

// ---------------- device scratch (no allocs allowed) ----------------
__device__ float g_bufA[N_NODES * HID_DIM];          // GEMM output (scaled)
__device__ __nv_bfloat16 g_hiA[N_NODES * HID_DIM];   // activation hi split (GEMM input)
__device__ __nv_bfloat16 g_loA[N_NODES * HID_DIM];   // activation lo split
__device__ __nv_bfloat16 g_W1tHi[IN_DIM * HID_DIM];
__device__ __nv_bfloat16 g_W1tLo[IN_DIM * HID_DIM];
__device__ __nv_bfloat16 g_W2tHi[HID_DIM * HID_DIM];
__device__ __nv_bfloat16 g_W2tLo[HID_DIM * HID_DIM];
__device__ __nv_bfloat16 g_W3tHi[HID_DIM * OUT_DIM];
__device__ __nv_bfloat16 g_W3tLo[HID_DIM * OUT_DIM];
__device__ float g_dinv[N_NODES];
__device__ int   g_cnt[N_NODES];
__device__ int   g_rowptr[N_NODES + 1];
__device__ int   g_cursor[N_NODES];
__device__ int   g_colsrc[N_EDGES];

// ---------------- preprocessing kernels ----------------
__global__ void zero_cnt_kernel(int* cnt, int n) {
    int i = blockIdx.x * blockDim.x + threadIdx.x;
    if (i < n) cnt[i] = 0;
}

__global__ void count_edges_kernel(const int* __restrict__ ei, int* cnt, int E) {
    int e = blockIdx.x * blockDim.x + threadIdx.x;
    if (e < E) {
        int d = ei[E + e];
        if (d >= 0 && d < N_NODES) atomicAdd(&cnt[d], 1);
    }
}

__global__ void scan_kernel(const int* __restrict__ cnt, int* rowptr, int* cursor,
                            float* dinv, int n) {
    __shared__ int ssum[1024];
    int tid = threadIdx.x;
    const int CH = (n + 1023) / 1024;
    int base = tid * CH;
    int local = 0;
    for (int i = 0; i < CH; i++) {
        int idx = base + i;
        if (idx < n) local += cnt[idx];
    }
    ssum[tid] = local;
    __syncthreads();
    for (int off = 1; off < 1024; off <<= 1) {
        int v = ssum[tid];
        int add = (tid >= off) ? ssum[tid - off] : 0;
        __syncthreads();
        ssum[tid] = v + add;
        __syncthreads();
    }
    int run = (tid > 0) ? ssum[tid - 1] : 0;
    for (int i = 0; i < CH; i++) {
        int idx = base + i;
        if (idx < n) {
            rowptr[idx] = run;
            cursor[idx] = run;
            int c = cnt[idx];
            run += c;
            dinv[idx] = rsqrtf((float)c + 1.0f);
        }
    }
    if (tid == 1023) rowptr[n] = run;
}

__global__ void fill_csr_kernel(const int* __restrict__ ei, int* cursor,
                                int* colsrc, int E) {
    int e = blockIdx.x * blockDim.x + threadIdx.x;
    if (e < E) {
        int s = ei[e];
        int d = ei[E + e];
        if (d >= 0 && d < N_NODES) {
            int p = atomicAdd(&cursor[d], 1);
            colsrc[p] = s;
        }
    }
}

// ---------------- split helpers ----------------
__device__ __forceinline__ void split2(float a, float b, uint32_t& hi, uint32_t& lo) {
    __nv_bfloat16 ha = __float2bfloat16(a);
    __nv_bfloat16 hb = __float2bfloat16(b);
    __nv_bfloat16 la = __float2bfloat16(a - __bfloat162float(ha));
    __nv_bfloat16 lb = __float2bfloat16(b - __bfloat162float(hb));
    hi = (uint32_t)__bfloat16_as_ushort(ha) | ((uint32_t)__bfloat16_as_ushort(hb) << 16);
    lo = (uint32_t)__bfloat16_as_ushort(la) | ((uint32_t)__bfloat16_as_ushort(lb) << 16);
}

// ---------------- fp32 -> bf16 hi/lo split (activations, flat) ----------------
__global__ void convert_split_kernel(const float* __restrict__ X,
                                     uint32_t* __restrict__ hi2,
                                     uint32_t* __restrict__ lo2, int total4) {
    int i = blockIdx.x * blockDim.x + threadIdx.x;
    if (i >= total4) return;
    float4 v = ((const float4*)X)[i];
    uint32_t h0, l0, h1, l1;
    split2(v.x, v.y, h0, l0);
    split2(v.z, v.w, h1, l1);
    hi2[2 * i] = h0; hi2[2 * i + 1] = h1;
    lo2[2 * i] = l0; lo2[2 * i + 1] = l1;
}

// ---------------- all three W [K,N] fp32 -> W^T [N,K] bf16 hi/lo ----------------
__global__ void convert_wt_all_kernel(const float* __restrict__ W1,
                                      const float* __restrict__ W2,
                                      const float* __restrict__ W3,
                                      __nv_bfloat16* __restrict__ h1, __nv_bfloat16* __restrict__ l1,
                                      __nv_bfloat16* __restrict__ h2, __nv_bfloat16* __restrict__ l2,
                                      __nv_bfloat16* __restrict__ h3, __nv_bfloat16* __restrict__ l3) {
    const int S1 = IN_DIM * HID_DIM;
    const int S2 = S1 + HID_DIM * HID_DIM;
    const int S3 = S2 + HID_DIM * OUT_DIM;
    int i = blockIdx.x * blockDim.x + threadIdx.x;
    if (i >= S3) return;
    if (i < S1) {
        int k = i / HID_DIM, n = i % HID_DIM;
        float v = W1[i];
        __nv_bfloat16 h = __float2bfloat16(v);
        h1[(size_t)n * IN_DIM + k] = h;
        l1[(size_t)n * IN_DIM + k] = __float2bfloat16(v - __bfloat162float(h));
    } else if (i < S2) {
        int j = i - S1;
        int k = j / HID_DIM, n = j % HID_DIM;
        float v = W2[j];
        __nv_bfloat16 h = __float2bfloat16(v);
        h2[(size_t)n * HID_DIM + k] = h;
        l2[(size_t)n * HID_DIM + k] = __float2bfloat16(v - __bfloat162float(h));
    } else {
        int j = i - S2;
        int k = j / OUT_DIM, n = j % OUT_DIM;
        float v = W3[j];
        __nv_bfloat16 h = __float2bfloat16(v);
        h3[(size_t)n * HID_DIM + k] = h;
        l3[(size_t)n * HID_DIM + k] = __float2bfloat16(v - __bfloat162float(h));
    }
}

// ---------------- mma.sync bf16 GEMM with ldmatrix operand loads ----------------
// C[r][c] = dinv[r] * sum_k A[r][k] * Wt[c][k], fp32 accum, bf16 hi/lo 3-mma split.
// CTA tile 128x128; 8 warps (2M x 4N), warp tile 64x32; BK=32 double-buffered cp.async.
#define RSU 20                         // smem row stride in u32 (16 data + 4 pad), 80B rows
#define TILE_U32 (128 * RSU)
#define GEMM_SMEM (2 * 4 * TILE_U32 * 4)   // 81920 bytes

__device__ __forceinline__ void cp16(uint32_t dst, const void* src, bool pred) {
    int sz = pred ? 16 : 0;
    asm volatile("cp.async.cg.shared.global [%0], [%1], 16, %2;"
                 :: "r"(dst), "l"(src), "r"(sz) : "memory");
}
__device__ __forceinline__ void mma_bf16(float c[4], const uint32_t a[4], const uint32_t b[2]) {
    asm volatile(
        "mma.sync.aligned.m16n8k16.row.col.f32.bf16.bf16.f32 "
        "{%0,%1,%2,%3}, {%4,%5,%6,%7}, {%8,%9}, {%0,%1,%2,%3};"
        : "+f"(c[0]), "+f"(c[1]), "+f"(c[2]), "+f"(c[3])
        : "r"(a[0]), "r"(a[1]), "r"(a[2]), "r"(a[3]), "r"(b[0]), "r"(b[1]));
}
__device__ __forceinline__ void ldsm_x4(uint32_t r[4], uint32_t addr) {
    asm volatile("ldmatrix.sync.aligned.m8n8.x4.shared.b16 {%0,%1,%2,%3}, [%4];"
                 : "=r"(r[0]), "=r"(r[1]), "=r"(r[2]), "=r"(r[3]) : "r"(addr));
}
__device__ __forceinline__ void ldsm_x2(uint32_t r[2], uint32_t addr) {
    asm volatile("ldmatrix.sync.aligned.m8n8.x2.shared.b16 {%0,%1}, [%2];"
                 : "=r"(r[0]), "=r"(r[1]) : "r"(addr));
}
__device__ __forceinline__ uint32_t smem_u32p(const void* p) {
    uint32_t a;
    asm("{ .reg .u64 t; cvta.to.shared.u64 t, %1; cvt.u32.u64 %0, t; }" : "=r"(a) : "l"(p));
    return a;
}

__global__ __launch_bounds__(256, 1) void gemm_mma_kernel(
    const uint32_t* __restrict__ Ahi2, const uint32_t* __restrict__ Alo2,
    const uint32_t* __restrict__ Bhi2, const uint32_t* __restrict__ Blo2,
    const float* __restrict__ dinv, float* __restrict__ C,
    int Mm, int Nn, int Kk)
{
    extern __shared__ __align__(16) uint32_t sm[];
    const uint32_t sb = smem_u32p(sm);

    const int tid = threadIdx.x;
    const int wid = tid >> 5;
    const int lid = tid & 31;
    const int g = lid >> 2;
    const int t = lid & 3;
    const int row0 = blockIdx.y * 128;
    const int col0 = blockIdx.x * 128;
    const int m0 = (wid & 1) * 64;
    const int n0 = (wid >> 1) * 32;
    const int Ku = Kk >> 1;

    // per-lane ldmatrix address components (byte offsets within a tile)
    const uint32_t aRow = (uint32_t)(m0 + (lid & 15));        // + mt*16
    const uint32_t aCol16 = (uint32_t)((lid >> 4) * 16);
    const uint32_t bRow = (uint32_t)(n0 + (lid & 7));         // + nt*8
    const uint32_t bCol16 = (uint32_t)(((lid >> 3) & 1) * 16);

    float acc[4][4][4];
#pragma unroll
    for (int mt = 0; mt < 4; mt++)
#pragma unroll
        for (int nt = 0; nt < 4; nt++)
#pragma unroll
            for (int i = 0; i < 4; i++) acc[mt][nt][i] = 0.0f;

    auto load_tiles = [&](int buf, int kt) {
        const int k0u = kt * 16;
#pragma unroll
        for (int half = 0; half < 2; half++) {
            int c = tid + half * 256;
            int row = c >> 2;
            int cq = (c & 3) * 4;
            int gr = row0 + row;
            bool inb = gr < Mm;
            int gra = inb ? gr : (Mm - 1);
            const uint32_t* sA = Ahi2 + (size_t)gra * Ku + k0u + cq;
            const uint32_t* sL = Alo2 + (size_t)gra * Ku + k0u + cq;
            uint32_t dst0 = sb + (uint32_t)(((buf * 4 + 0) * TILE_U32 + row * RSU + cq) * 4);
            uint32_t dst1 = sb + (uint32_t)(((buf * 4 + 1) * TILE_U32 + row * RSU + cq) * 4);
            cp16(dst0, sA, inb);
            cp16(dst1, sL, inb);
            int gn = col0 + row;
            const uint32_t* sBh = Bhi2 + (size_t)gn * Ku + k0u + cq;
            const uint32_t* sBl = Blo2 + (size_t)gn * Ku + k0u + cq;
            uint32_t dst2 = sb + (uint32_t)(((buf * 4 + 2) * TILE_U32 + row * RSU + cq) * 4);
            uint32_t dst3 = sb + (uint32_t)(((buf * 4 + 3) * TILE_U32 + row * RSU + cq) * 4);
            cp16(dst2, sBh, true);
            cp16(dst3, sBl, true);
        }
        asm volatile("cp.async.commit_group;" ::: "memory");
    };

    const int nkt = Kk / 32;
    load_tiles(0, 0);

    for (int kt = 0; kt < nkt; kt++) {
        int buf = kt & 1;
        if (kt + 1 < nkt) {
            load_tiles(buf ^ 1, kt + 1);
            asm volatile("cp.async.wait_group 1;" ::: "memory");
        } else {
            asm volatile("cp.async.wait_group 0;" ::: "memory");
        }
        __syncthreads();

        const uint32_t oAh = sb + (uint32_t)((buf * 4 + 0) * TILE_U32 * 4);
        const uint32_t oAl = sb + (uint32_t)((buf * 4 + 1) * TILE_U32 * 4);
        const uint32_t oBh = sb + (uint32_t)((buf * 4 + 2) * TILE_U32 * 4);
        const uint32_t oBl = sb + (uint32_t)((buf * 4 + 3) * TILE_U32 * 4);

#pragma unroll
        for (int ks = 0; ks < 2; ks++) {
            const uint32_t kbB = (uint32_t)(ks * 32);    // bytes: 8 u32
            uint32_t ah[4][4], al[4][4], bh[4][2], bl[4][2];
#pragma unroll
            for (int mt = 0; mt < 4; mt++) {
                uint32_t ra = (aRow + mt * 16) * (RSU * 4) + kbB + aCol16;
                ldsm_x4(ah[mt], oAh + ra);
                ldsm_x4(al[mt], oAl + ra);
            }
#pragma unroll
            for (int nt = 0; nt < 4; nt++) {
                uint32_t rb = (bRow + nt * 8) * (RSU * 4) + kbB + bCol16;
                ldsm_x2(bh[nt], oBh + rb);
                ldsm_x2(bl[nt], oBl + rb);
            }
#pragma unroll
            for (int mt = 0; mt < 4; mt++)
#pragma unroll
                for (int nt = 0; nt < 4; nt++) {
                    mma_bf16(acc[mt][nt], ah[mt], bh[nt]);   // hi*hi
                    mma_bf16(acc[mt][nt], al[mt], bh[nt]);   // lo*hi
                    mma_bf16(acc[mt][nt], ah[mt], bl[nt]);   // hi*lo
                }
        }
        __syncthreads();
    }

    // ---- epilogue: direct register -> gmem with dinv row scale ----
#pragma unroll
    for (int mt = 0; mt < 4; mt++) {
        int r0 = row0 + m0 + mt * 16 + g;
        int r1 = r0 + 8;
        float s0 = (r0 < Mm) ? dinv[r0] : 0.0f;
        float s1 = (r1 < Mm) ? dinv[r1] : 0.0f;
#pragma unroll
        for (int nt = 0; nt < 4; nt++) {
            int cn = col0 + n0 + nt * 8 + t * 2;
            if (r0 < Mm) {
                float2 v0 = make_float2(acc[mt][nt][0] * s0, acc[mt][nt][1] * s0);
                *(float2*)(C + (size_t)r0 * Nn + cn) = v0;
            }
            if (r1 < Mm) {
                float2 v1 = make_float2(acc[mt][nt][2] * s1, acc[mt][nt][3] * s1);
                *(float2*)(C + (size_t)r1 * Nn + cn) = v1;
            }
        }
    }
}

// ---------------- aggregation core: v = tanh/id( dinv[i]*(G[i] + sum G[src]) + b ) ----------------
template <int APPLY_TANH, int SPLIT_OUT>
__global__ void agg_kernel_t(const float* __restrict__ G,
                             const float* __restrict__ bias,
                             const float* __restrict__ dinv,
                             const int* __restrict__ rowptr,
                             const int* __restrict__ colsrc,
                             float* __restrict__ outF,
                             uint2* __restrict__ outHi,
                             uint2* __restrict__ outLo,
                             int F4)
{
    int i = blockIdx.x;
    int t = threadIdx.x;
    const float4* G4 = (const float4*)G;

    float4 acc = __ldg(&G4[(size_t)i * F4 + t]);

    int e   = rowptr[i];
    int end = rowptr[i + 1];
    for (; e + 4 <= end; e += 4) {
        int s0 = __ldg(&colsrc[e + 0]);
        int s1 = __ldg(&colsrc[e + 1]);
        int s2 = __ldg(&colsrc[e + 2]);
        int s3 = __ldg(&colsrc[e + 3]);
        float4 v0 = __ldg(&G4[(size_t)s0 * F4 + t]);
        float4 v1 = __ldg(&G4[(size_t)s1 * F4 + t]);
        float4 v2 = __ldg(&G4[(size_t)s2 * F4 + t]);
        float4 v3 = __ldg(&G4[(size_t)s3 * F4 + t]);
        acc.x += v0.x + v1.x + v2.x + v3.x;
        acc.y += v0.y + v1.y + v2.y + v3.y;
        acc.z += v0.z + v1.z + v2.z + v3.z;
        acc.w += v0.w + v1.w + v2.w + v3.w;
    }
    for (; e < end; ++e) {
        int s = __ldg(&colsrc[e]);
        float4 v = __ldg(&G4[(size_t)s * F4 + t]);
        acc.x += v.x; acc.y += v.y; acc.z += v.z; acc.w += v.w;
    }

    float di = dinv[i];
    float4 bb = ((const float4*)bias)[t];
    float4 r;
    r.x = fmaf(acc.x, di, bb.x);
    r.y = fmaf(acc.y, di, bb.y);
    r.z = fmaf(acc.z, di, bb.z);
    r.w = fmaf(acc.w, di, bb.w);
    if (APPLY_TANH) {
        r.x = tanhf(r.x); r.y = tanhf(r.y);
        r.z = tanhf(r.z); r.w = tanhf(r.w);
    }
    if (SPLIT_OUT) {
        uint32_t h0, l0, h1, l1;
        split2(r.x, r.y, h0, l0);
        split2(r.z, r.w, h1, l1);
        outHi[(size_t)i * F4 + t] = make_uint2(h0, h1);
        outLo[(size_t)i * F4 + t] = make_uint2(l0, l1);
    } else {
        ((float4*)outF)[(size_t)i * F4 + t] = r;
    }
}

// ---------------- launch ----------------
extern "C" void kernel_launch(void* const* d_in, const int* in_sizes, int n_in,
                              void* d_out, int out_size) {
    const float* x  = (const float*)d_in[0];
    const float* W1 = (const float*)d_in[1];
    const float* b1 = (const float*)d_in[2];
    const float* W2 = (const float*)d_in[3];
    const float* b2 = (const float*)d_in[4];
    const float* W3 = (const float*)d_in[5];
    const float* b3 = (const float*)d_in[6];
    const int*   ei = (const int*)d_in[7];    // int32 edge_index [2, E]
    float* out = (float*)d_out;

    const int N = N_NODES;
    const int E = in_sizes[7] / 2;

    float *bufA, *dinv;
    int *cnt, *rowptr, *cursor, *colsrc;
    __nv_bfloat16 *hiA, *loA, *w1h, *w1l, *w2h, *w2l, *w3h, *w3l;
    cudaGetSymbolAddress((void**)&bufA,   g_bufA);
    cudaGetSymbolAddress((void**)&dinv,   g_dinv);
    cudaGetSymbolAddress((void**)&cnt,    g_cnt);
    cudaGetSymbolAddress((void**)&rowptr, g_rowptr);
    cudaGetSymbolAddress((void**)&cursor, g_cursor);
    cudaGetSymbolAddress((void**)&colsrc, g_colsrc);
    cudaGetSymbolAddress((void**)&hiA,    g_hiA);
    cudaGetSymbolAddress((void**)&loA,    g_loA);
    cudaGetSymbolAddress((void**)&w1h,    g_W1tHi);
    cudaGetSymbolAddress((void**)&w1l,    g_W1tLo);
    cudaGetSymbolAddress((void**)&w2h,    g_W2tHi);
    cudaGetSymbolAddress((void**)&w2l,    g_W2tLo);
    cudaGetSymbolAddress((void**)&w3h,    g_W3tHi);
    cudaGetSymbolAddress((void**)&w3l,    g_W3tLo);

    static bool attr_set = false;
    if (!attr_set) {
        cudaFuncSetAttribute(gemm_mma_kernel, cudaFuncAttributeMaxDynamicSharedMemorySize, GEMM_SMEM);
        attr_set = true;
    }

    // --- preprocessing: degrees + CSR by dst ---
    zero_cnt_kernel<<<(N + 255) / 256, 256>>>(cnt, N);
    count_edges_kernel<<<(E + 255) / 256, 256>>>(ei, cnt, E);
    scan_kernel<<<1, 1024>>>(cnt, rowptr, cursor, dinv, N);
    fill_csr_kernel<<<(E + 255) / 256, 256>>>(ei, cursor, colsrc, E);

    // --- one-shot conversions ---
    const int WTOT = IN_DIM * HID_DIM + HID_DIM * HID_DIM + HID_DIM * OUT_DIM;
    convert_wt_all_kernel<<<(WTOT + 255) / 256, 256>>>(W1, W2, W3, w1h, w1l, w2h, w2l, w3h, w3l);
    convert_split_kernel<<<(N * IN_DIM / 4 + 255) / 256, 256>>>(x, (uint32_t*)hiA, (uint32_t*)loA, N * IN_DIM / 4);

    const int MT = (N + 127) / 128;

    // --- layer 1 ---
    {
        dim3 grid(HID_DIM / 128, MT);
        gemm_mma_kernel<<<grid, 256, GEMM_SMEM>>>((uint32_t*)hiA, (uint32_t*)loA,
                                                  (uint32_t*)w1h, (uint32_t*)w1l,
                                                  dinv, bufA, N, HID_DIM, IN_DIM);
        agg_kernel_t<1, 1><<<N, HID_DIM / 4>>>(bufA, b1, dinv, rowptr, colsrc,
                                               nullptr, (uint2*)hiA, (uint2*)loA, HID_DIM / 4);
    }
    // --- layer 2 ---
    {
        dim3 grid(HID_DIM / 128, MT);
        gemm_mma_kernel<<<grid, 256, GEMM_SMEM>>>((uint32_t*)hiA, (uint32_t*)loA,
                                                  (uint32_t*)w2h, (uint32_t*)w2l,
                                                  dinv, bufA, N, HID_DIM, HID_DIM);
        agg_kernel_t<1, 1><<<N, HID_DIM / 4>>>(bufA, b2, dinv, rowptr, colsrc,
                                               nullptr, (uint2*)hiA, (uint2*)loA, HID_DIM / 4);
    }
    // --- layer 3 ---
    {
        dim3 grid(OUT_DIM / 128, MT);
        gemm_mma_kernel<<<grid, 256, GEMM_SMEM>>>((uint32_t*)hiA, (uint32_t*)loA,
                                                  (uint32_t*)w3h, (uint32_t*)w3l,
                                                  dinv, bufA, N, OUT_DIM, HID_DIM);
        agg_kernel_t<0, 0><<<N, OUT_DIM / 4>>>(bufA, b3, dinv, rowptr, colsrc,
                                               out, nullptr, nullptr, OUT_DIM / 4);
    }
}

// round 6
// speedup vs baseline: 2.2288x; 1.1537x over previous
#include <cuda_runtime.h>
#include <cuda_bf16.h>
#include <math.h>
#include <stdint.h>

// ---------------- problem constants ----------------
#define N_NODES 10000
#define N_EDGES 160000
#define IN_DIM  256
#define HID_DIM 512
#define OUT_DIM 256

// ---------------- device scratch (no allocs allowed) ----------------
__device__ float g_bufA[N_NODES * HID_DIM];          // GEMM output (scaled)
__device__ __nv_bfloat16 g_hiA[N_NODES * HID_DIM];   // activation hi split (GEMM input)
__device__ __nv_bfloat16 g_loA[N_NODES * HID_DIM];   // activation lo split
__device__ __nv_bfloat16 g_W1tHi[IN_DIM * HID_DIM];
__device__ __nv_bfloat16 g_W1tLo[IN_DIM * HID_DIM];
__device__ __nv_bfloat16 g_W2tHi[HID_DIM * HID_DIM];
__device__ __nv_bfloat16 g_W2tLo[HID_DIM * HID_DIM];
__device__ __nv_bfloat16 g_W3tHi[HID_DIM * OUT_DIM];
__device__ __nv_bfloat16 g_W3tLo[HID_DIM * OUT_DIM];
__device__ float g_dinv[N_NODES];
__device__ int   g_cnt[N_NODES];
__device__ int   g_rowptr[N_NODES + 1];
__device__ int   g_cursor[N_NODES];
__device__ int   g_colsrc[N_EDGES];

// ---------------- split helper ----------------
__device__ __forceinline__ void split2(float a, float b, uint32_t& hi, uint32_t& lo) {
    __nv_bfloat16 ha = __float2bfloat16(a);
    __nv_bfloat16 hb = __float2bfloat16(b);
    __nv_bfloat16 la = __float2bfloat16(a - __bfloat162float(ha));
    __nv_bfloat16 lb = __float2bfloat16(b - __bfloat162float(hb));
    hi = (uint32_t)__bfloat16_as_ushort(ha) | ((uint32_t)__bfloat16_as_ushort(hb) << 16);
    lo = (uint32_t)__bfloat16_as_ushort(la) | ((uint32_t)__bfloat16_as_ushort(lb) << 16);
}

// ---------------- fused one-shot prep: W1/W2/W3 -> W^T hi/lo, x -> hi/lo, cnt zero ----------------
#define WTOT (IN_DIM * HID_DIM + HID_DIM * HID_DIM + HID_DIM * OUT_DIM)   // 524288
#define XTOT4 (N_NODES * IN_DIM / 4)                                     // 640000
__global__ void fused_prep_kernel(const float* __restrict__ W1, const float* __restrict__ W2,
                                  const float* __restrict__ W3,
                                  __nv_bfloat16* __restrict__ h1, __nv_bfloat16* __restrict__ l1,
                                  __nv_bfloat16* __restrict__ h2, __nv_bfloat16* __restrict__ l2,
                                  __nv_bfloat16* __restrict__ h3, __nv_bfloat16* __restrict__ l3,
                                  const float* __restrict__ x,
                                  uint32_t* __restrict__ hiX, uint32_t* __restrict__ loX,
                                  int* __restrict__ cnt) {
    const int S1 = IN_DIM * HID_DIM;
    const int S2 = S1 + HID_DIM * HID_DIM;
    int i = blockIdx.x * blockDim.x + threadIdx.x;
    if (i < WTOT) {
        if (i < S1) {
            int k = i / HID_DIM, n = i % HID_DIM;
            float v = W1[i];
            __nv_bfloat16 h = __float2bfloat16(v);
            h1[(size_t)n * IN_DIM + k] = h;
            l1[(size_t)n * IN_DIM + k] = __float2bfloat16(v - __bfloat162float(h));
        } else if (i < S2) {
            int j = i - S1;
            int k = j / HID_DIM, n = j % HID_DIM;
            float v = W2[j];
            __nv_bfloat16 h = __float2bfloat16(v);
            h2[(size_t)n * HID_DIM + k] = h;
            l2[(size_t)n * HID_DIM + k] = __float2bfloat16(v - __bfloat162float(h));
        } else {
            int j = i - S2;
            int k = j / OUT_DIM, n = j % OUT_DIM;
            float v = W3[j];
            __nv_bfloat16 h = __float2bfloat16(v);
            h3[(size_t)n * HID_DIM + k] = h;
            l3[(size_t)n * HID_DIM + k] = __float2bfloat16(v - __bfloat162float(h));
        }
    } else if (i < WTOT + XTOT4) {
        int j = i - WTOT;
        float4 v = ((const float4*)x)[j];
        uint32_t h0, l0, h1u, l1u;
        split2(v.x, v.y, h0, l0);
        split2(v.z, v.w, h1u, l1u);
        hiX[2 * j] = h0; hiX[2 * j + 1] = h1u;
        loX[2 * j] = l0; loX[2 * j + 1] = l1u;
    } else if (i < WTOT + XTOT4 + N_NODES) {
        cnt[i - WTOT - XTOT4] = 0;
    }
}

// ---------------- preprocessing kernels ----------------
__global__ void count_edges_kernel(const int* __restrict__ ei, int* cnt, int E) {
    int e = blockIdx.x * blockDim.x + threadIdx.x;
    if (e < E) {
        int d = ei[E + e];
        if (d >= 0 && d < N_NODES) atomicAdd(&cnt[d], 1);
    }
}

__global__ void scan_kernel(const int* __restrict__ cnt, int* rowptr, int* cursor,
                            float* dinv, int n) {
    __shared__ int ssum[1024];
    int tid = threadIdx.x;
    const int CH = (n + 1023) / 1024;
    int base = tid * CH;
    int local = 0;
    for (int i = 0; i < CH; i++) {
        int idx = base + i;
        if (idx < n) local += cnt[idx];
    }
    ssum[tid] = local;
    __syncthreads();
    for (int off = 1; off < 1024; off <<= 1) {
        int v = ssum[tid];
        int add = (tid >= off) ? ssum[tid - off] : 0;
        __syncthreads();
        ssum[tid] = v + add;
        __syncthreads();
    }
    int run = (tid > 0) ? ssum[tid - 1] : 0;
    for (int i = 0; i < CH; i++) {
        int idx = base + i;
        if (idx < n) {
            rowptr[idx] = run;
            cursor[idx] = run;
            int c = cnt[idx];
            run += c;
            dinv[idx] = rsqrtf((float)c + 1.0f);
        }
    }
    if (tid == 1023) rowptr[n] = run;
}

__global__ void fill_csr_kernel(const int* __restrict__ ei, int* cursor,
                                int* colsrc, int E) {
    int e = blockIdx.x * blockDim.x + threadIdx.x;
    if (e < E) {
        int s = ei[e];
        int d = ei[E + e];
        if (d >= 0 && d < N_NODES) {
            int p = atomicAdd(&cursor[d], 1);
            colsrc[p] = s;
        }
    }
}

// ---------------- mma.sync bf16 GEMM, XOR-swizzled smem, 2 CTAs/SM ----------------
// C[r][c] = dinv[r] * sum_k A[r][k] * Wt[c][k], fp32 accum, bf16 hi/lo 3-mma split.
// CTA tile 128x128; 8 warps (2M x 4N), warp tile 64x32; BK=32 double-buffered cp.async.
// SMEM tile: 128 rows x 64B, XOR swizzle over 128B super-rows -> 8KB/tile, 4 tiles/stage,
// 2 stages = 64KB total -> 2 CTAs per SM.
#define TILE_B 8192
#define STAGE_B (4 * TILE_B)       // 32768
#define GEMM_SMEM (2 * STAGE_B)    // 65536

__device__ __forceinline__ uint32_t swz(uint32_t row, uint32_t c) {
    // byte offset of 16B chunk c (0..3) of row (0..127) within an 8KB tile
    return ((row >> 1) << 7) | ((((((row & 1u) << 2) | c)) ^ ((row >> 1) & 3u)) << 4);
}
__device__ __forceinline__ void cp16(uint32_t dst, const void* src, bool pred) {
    int sz = pred ? 16 : 0;
    asm volatile("cp.async.cg.shared.global [%0], [%1], 16, %2;"
                 :: "r"(dst), "l"(src), "r"(sz) : "memory");
}
__device__ __forceinline__ void mma_bf16(float c[4], const uint32_t a[4], const uint32_t b[2]) {
    asm volatile(
        "mma.sync.aligned.m16n8k16.row.col.f32.bf16.bf16.f32 "
        "{%0,%1,%2,%3}, {%4,%5,%6,%7}, {%8,%9}, {%0,%1,%2,%3};"
        : "+f"(c[0]), "+f"(c[1]), "+f"(c[2]), "+f"(c[3])
        : "r"(a[0]), "r"(a[1]), "r"(a[2]), "r"(a[3]), "r"(b[0]), "r"(b[1]));
}
__device__ __forceinline__ void ldsm_x4(uint32_t r[4], uint32_t addr) {
    asm volatile("ldmatrix.sync.aligned.m8n8.x4.shared.b16 {%0,%1,%2,%3}, [%4];"
                 : "=r"(r[0]), "=r"(r[1]), "=r"(r[2]), "=r"(r[3]) : "r"(addr));
}
__device__ __forceinline__ void ldsm_x2(uint32_t r[2], uint32_t addr) {
    asm volatile("ldmatrix.sync.aligned.m8n8.x2.shared.b16 {%0,%1}, [%2];"
                 : "=r"(r[0]), "=r"(r[1]) : "r"(addr));
}
__device__ __forceinline__ uint32_t smem_u32p(const void* p) {
    uint32_t a;
    asm("{ .reg .u64 t; cvta.to.shared.u64 t, %1; cvt.u32.u64 %0, t; }" : "=r"(a) : "l"(p));
    return a;
}

__global__ __launch_bounds__(256, 2) void gemm_mma_kernel(
    const uint32_t* __restrict__ Ahi2, const uint32_t* __restrict__ Alo2,
    const uint32_t* __restrict__ Bhi2, const uint32_t* __restrict__ Blo2,
    const float* __restrict__ dinv, float* __restrict__ C,
    int Mm, int Nn, int Kk)
{
    extern __shared__ __align__(16) uint32_t sm[];
    const uint32_t sb = smem_u32p(sm);

    const int tid = threadIdx.x;
    const int wid = tid >> 5;
    const int lid = tid & 31;
    const int g = lid >> 2;
    const int t = lid & 3;
    const int row0 = blockIdx.y * 128;
    const int col0 = blockIdx.x * 128;
    const int m0 = (wid & 1) * 64;
    const int n0 = (wid >> 1) * 32;
    const int Ku = Kk >> 1;

    float acc[4][4][4];
#pragma unroll
    for (int mt = 0; mt < 4; mt++)
#pragma unroll
        for (int nt = 0; nt < 4; nt++)
#pragma unroll
            for (int i = 0; i < 4; i++) acc[mt][nt][i] = 0.0f;

    // loader: 4 tiles x 128 rows x 4 chunks = 2048 chunks, 256 threads -> 8 iters
    auto load_tiles = [&](int buf, int kt) {
        const int k0u = kt * 16;
#pragma unroll
        for (int it = 0; it < 8; it++) {
            int c = it * 256 + tid;
            int tile = c >> 9;            // compile-time per it (2 iters per tile)
            int r = (c >> 2) & 127;
            int ch = c & 3;
            uint32_t dst = sb + (uint32_t)(buf * STAGE_B + tile * TILE_B) + swz((uint32_t)r, (uint32_t)ch);
            const uint32_t* src;
            bool p = true;
            if (tile < 2) {
                int gr = row0 + r;
                p = gr < Mm;
                int gra = p ? gr : 0;
                src = (tile == 0 ? Ahi2 : Alo2) + (size_t)gra * Ku + k0u + ch * 4;
            } else {
                int gn = col0 + r;
                src = (tile == 2 ? Bhi2 : Blo2) + (size_t)gn * Ku + k0u + ch * 4;
            }
            cp16(dst, src, p);
        }
        asm volatile("cp.async.commit_group;" ::: "memory");
    };

    const int nkt = Kk / 32;
    load_tiles(0, 0);

    const uint32_t aR = (uint32_t)(m0 + (lid & 15));
    const uint32_t aC = (uint32_t)(lid >> 4);          // + ks*2
    const uint32_t bR = (uint32_t)(n0 + (lid & 7));
    const uint32_t bC = (uint32_t)((lid >> 3) & 1);    // + ks*2

    for (int kt = 0; kt < nkt; kt++) {
        int buf = kt & 1;
        if (kt + 1 < nkt) {
            load_tiles(buf ^ 1, kt + 1);
            asm volatile("cp.async.wait_group 1;" ::: "memory");
        } else {
            asm volatile("cp.async.wait_group 0;" ::: "memory");
        }
        __syncthreads();

        const uint32_t base = sb + (uint32_t)(buf * STAGE_B);

#pragma unroll
        for (int ks = 0; ks < 2; ks++) {
            uint32_t ah[4][4], al[4][4];
#pragma unroll
            for (int mt = 0; mt < 4; mt++) {
                uint32_t off = swz(aR + mt * 16, aC + ks * 2);
                ldsm_x4(ah[mt], base + off);              // A hi tile at +0
                ldsm_x4(al[mt], base + TILE_B + off);     // A lo tile
            }
#pragma unroll
            for (int nt = 0; nt < 4; nt++) {
                uint32_t off = swz(bR + nt * 8, bC + ks * 2);
                uint32_t bh[2], bl[2];
                ldsm_x2(bh, base + 2 * TILE_B + off);
                ldsm_x2(bl, base + 3 * TILE_B + off);
#pragma unroll
                for (int mt = 0; mt < 4; mt++) {
                    mma_bf16(acc[mt][nt], ah[mt], bh);    // hi*hi
                    mma_bf16(acc[mt][nt], al[mt], bh);    // lo*hi
                    mma_bf16(acc[mt][nt], ah[mt], bl);    // hi*lo
                }
            }
        }
        __syncthreads();
    }

    // ---- epilogue: direct register -> gmem with dinv row scale ----
#pragma unroll
    for (int mt = 0; mt < 4; mt++) {
        int r0 = row0 + m0 + mt * 16 + g;
        int r1 = r0 + 8;
        float s0 = (r0 < Mm) ? dinv[r0] : 0.0f;
        float s1 = (r1 < Mm) ? dinv[r1] : 0.0f;
#pragma unroll
        for (int nt = 0; nt < 4; nt++) {
            int cn = col0 + n0 + nt * 8 + t * 2;
            if (r0 < Mm) {
                float2 v0 = make_float2(acc[mt][nt][0] * s0, acc[mt][nt][1] * s0);
                *(float2*)(C + (size_t)r0 * Nn + cn) = v0;
            }
            if (r1 < Mm) {
                float2 v1 = make_float2(acc[mt][nt][2] * s1, acc[mt][nt][3] * s1);
                *(float2*)(C + (size_t)r1 * Nn + cn) = v1;
            }
        }
    }
}

// ---------------- aggregation: v = tanh/id( dinv[i]*(G[i] + sum G[src]) + b ) ----------------
template <int APPLY_TANH, int SPLIT_OUT>
__global__ void agg_kernel_t(const float* __restrict__ G,
                             const float* __restrict__ bias,
                             const float* __restrict__ dinv,
                             const int* __restrict__ rowptr,
                             const int* __restrict__ colsrc,
                             float* __restrict__ outF,
                             uint2* __restrict__ outHi,
                             uint2* __restrict__ outLo,
                             int F4)
{
    int i = blockIdx.x;
    int t = threadIdx.x;
    const float4* G4 = (const float4*)G;

    float4 acc = __ldg(&G4[(size_t)i * F4 + t]);

    int e   = rowptr[i];
    int end = rowptr[i + 1];
    for (; e + 4 <= end; e += 4) {
        int s0 = __ldg(&colsrc[e + 0]);
        int s1 = __ldg(&colsrc[e + 1]);
        int s2 = __ldg(&colsrc[e + 2]);
        int s3 = __ldg(&colsrc[e + 3]);
        float4 v0 = __ldg(&G4[(size_t)s0 * F4 + t]);
        float4 v1 = __ldg(&G4[(size_t)s1 * F4 + t]);
        float4 v2 = __ldg(&G4[(size_t)s2 * F4 + t]);
        float4 v3 = __ldg(&G4[(size_t)s3 * F4 + t]);
        acc.x += v0.x + v1.x + v2.x + v3.x;
        acc.y += v0.y + v1.y + v2.y + v3.y;
        acc.z += v0.z + v1.z + v2.z + v3.z;
        acc.w += v0.w + v1.w + v2.w + v3.w;
    }
    for (; e < end; ++e) {
        int s = __ldg(&colsrc[e]);
        float4 v = __ldg(&G4[(size_t)s * F4 + t]);
        acc.x += v.x; acc.y += v.y; acc.z += v.z; acc.w += v.w;
    }

    float di = dinv[i];
    float4 bb = ((const float4*)bias)[t];
    float4 r;
    r.x = fmaf(acc.x, di, bb.x);
    r.y = fmaf(acc.y, di, bb.y);
    r.z = fmaf(acc.z, di, bb.z);
    r.w = fmaf(acc.w, di, bb.w);
    if (APPLY_TANH) {
        r.x = tanhf(r.x); r.y = tanhf(r.y);
        r.z = tanhf(r.z); r.w = tanhf(r.w);
    }
    if (SPLIT_OUT) {
        uint32_t h0, l0, h1, l1;
        split2(r.x, r.y, h0, l0);
        split2(r.z, r.w, h1, l1);
        outHi[(size_t)i * F4 + t] = make_uint2(h0, h1);
        outLo[(size_t)i * F4 + t] = make_uint2(l0, l1);
    } else {
        ((float4*)outF)[(size_t)i * F4 + t] = r;
    }
}

// ---------------- launch ----------------
extern "C" void kernel_launch(void* const* d_in, const int* in_sizes, int n_in,
                              void* d_out, int out_size) {
    const float* x  = (const float*)d_in[0];
    const float* W1 = (const float*)d_in[1];
    const float* b1 = (const float*)d_in[2];
    const float* W2 = (const float*)d_in[3];
    const float* b2 = (const float*)d_in[4];
    const float* W3 = (const float*)d_in[5];
    const float* b3 = (const float*)d_in[6];
    const int*   ei = (const int*)d_in[7];    // int32 edge_index [2, E]
    float* out = (float*)d_out;

    const int N = N_NODES;
    const int E = in_sizes[7] / 2;

    float *bufA, *dinv;
    int *cnt, *rowptr, *cursor, *colsrc;
    __nv_bfloat16 *hiA, *loA, *w1h, *w1l, *w2h, *w2l, *w3h, *w3l;
    cudaGetSymbolAddress((void**)&bufA,   g_bufA);
    cudaGetSymbolAddress((void**)&dinv,   g_dinv);
    cudaGetSymbolAddress((void**)&cnt,    g_cnt);
    cudaGetSymbolAddress((void**)&rowptr, g_rowptr);
    cudaGetSymbolAddress((void**)&cursor, g_cursor);
    cudaGetSymbolAddress((void**)&colsrc, g_colsrc);
    cudaGetSymbolAddress((void**)&hiA,    g_hiA);
    cudaGetSymbolAddress((void**)&loA,    g_loA);
    cudaGetSymbolAddress((void**)&w1h,    g_W1tHi);
    cudaGetSymbolAddress((void**)&w1l,    g_W1tLo);
    cudaGetSymbolAddress((void**)&w2h,    g_W2tHi);
    cudaGetSymbolAddress((void**)&w2l,    g_W2tLo);
    cudaGetSymbolAddress((void**)&w3h,    g_W3tHi);
    cudaGetSymbolAddress((void**)&w3l,    g_W3tLo);

    static bool attr_set = false;
    if (!attr_set) {
        cudaFuncSetAttribute(gemm_mma_kernel, cudaFuncAttributeMaxDynamicSharedMemorySize, GEMM_SMEM);
        attr_set = true;
    }

    // --- fused one-shot prep (W splits, x split, cnt zero) ---
    {
        int total = WTOT + XTOT4 + N;
        fused_prep_kernel<<<(total + 255) / 256, 256>>>(W1, W2, W3, w1h, w1l, w2h, w2l, w3h, w3l,
                                                        x, (uint32_t*)hiA, (uint32_t*)loA, cnt);
    }
    // --- CSR by dst ---
    count_edges_kernel<<<(E + 255) / 256, 256>>>(ei, cnt, E);
    scan_kernel<<<1, 1024>>>(cnt, rowptr, cursor, dinv, N);
    fill_csr_kernel<<<(E + 255) / 256, 256>>>(ei, cursor, colsrc, E);

    const int MT = (N + 127) / 128;

    // --- layer 1 ---
    {
        dim3 grid(HID_DIM / 128, MT);
        gemm_mma_kernel<<<grid, 256, GEMM_SMEM>>>((uint32_t*)hiA, (uint32_t*)loA,
                                                  (uint32_t*)w1h, (uint32_t*)w1l,
                                                  dinv, bufA, N, HID_DIM, IN_DIM);
        agg_kernel_t<1, 1><<<N, HID_DIM / 4>>>(bufA, b1, dinv, rowptr, colsrc,
                                               nullptr, (uint2*)hiA, (uint2*)loA, HID_DIM / 4);
    }
    // --- layer 2 ---
    {
        dim3 grid(HID_DIM / 128, MT);
        gemm_mma_kernel<<<grid, 256, GEMM_SMEM>>>((uint32_t*)hiA, (uint32_t*)loA,
                                                  (uint32_t*)w2h, (uint32_t*)w2l,
                                                  dinv, bufA, N, HID_DIM, HID_DIM);
        agg_kernel_t<1, 1><<<N, HID_DIM / 4>>>(bufA, b2, dinv, rowptr, colsrc,
                                               nullptr, (uint2*)hiA, (uint2*)loA, HID_DIM / 4);
    }
    // --- layer 3 ---
    {
        dim3 grid(OUT_DIM / 128, MT);
        gemm_mma_kernel<<<grid, 256, GEMM_SMEM>>>((uint32_t*)hiA, (uint32_t*)loA,
                                                  (uint32_t*)w3h, (uint32_t*)w3l,
                                                  dinv, bufA, N, OUT_DIM, HID_DIM);
        agg_kernel_t<0, 0><<<N, OUT_DIM / 4>>>(bufA, b3, dinv, rowptr, colsrc,
                                               out, nullptr, nullptr, OUT_DIM / 4);
    }
}

// round 7
// speedup vs baseline: 2.2313x; 1.0011x over previous
#include <cuda_runtime.h>
#include <cuda_bf16.h>
#include <math.h>
#include <stdint.h>

// ---------------- problem constants ----------------
#define N_NODES 10000
#define N_EDGES 160000
#define IN_DIM  256
#define HID_DIM 512
#define OUT_DIM 256

// ---------------- device scratch (no allocs allowed) ----------------
__device__ float g_bufA[N_NODES * HID_DIM];          // GEMM output (scaled)
__device__ __nv_bfloat16 g_hiA[N_NODES * HID_DIM];   // activation hi split (GEMM input)
__device__ __nv_bfloat16 g_loA[N_NODES * HID_DIM];   // activation lo split
__device__ __nv_bfloat16 g_W1tHi[IN_DIM * HID_DIM];
__device__ __nv_bfloat16 g_W1tLo[IN_DIM * HID_DIM];
__device__ __nv_bfloat16 g_W2tHi[HID_DIM * HID_DIM];
__device__ __nv_bfloat16 g_W2tLo[HID_DIM * HID_DIM];
__device__ __nv_bfloat16 g_W3tHi[HID_DIM * OUT_DIM];
__device__ __nv_bfloat16 g_W3tLo[HID_DIM * OUT_DIM];
__device__ float g_dinv[N_NODES];
__device__ int   g_cnt[N_NODES];
__device__ int   g_rowptr[N_NODES + 1];
__device__ int   g_cursor[N_NODES];
__device__ int   g_colsrc[N_EDGES];

// ---------------- split helper ----------------
__device__ __forceinline__ void split2(float a, float b, uint32_t& hi, uint32_t& lo) {
    __nv_bfloat16 ha = __float2bfloat16(a);
    __nv_bfloat16 hb = __float2bfloat16(b);
    __nv_bfloat16 la = __float2bfloat16(a - __bfloat162float(ha));
    __nv_bfloat16 lb = __float2bfloat16(b - __bfloat162float(hb));
    hi = (uint32_t)__bfloat16_as_ushort(ha) | ((uint32_t)__bfloat16_as_ushort(hb) << 16);
    lo = (uint32_t)__bfloat16_as_ushort(la) | ((uint32_t)__bfloat16_as_ushort(lb) << 16);
}

// ---------------- fused one-shot prep: W1/W2/W3 -> W^T hi/lo, x -> hi/lo, cnt zero ----------------
#define WTOT (IN_DIM * HID_DIM + HID_DIM * HID_DIM + HID_DIM * OUT_DIM)   // 524288
#define XTOT4 (N_NODES * IN_DIM / 4)                                     // 640000
__global__ void fused_prep_kernel(const float* __restrict__ W1, const float* __restrict__ W2,
                                  const float* __restrict__ W3,
                                  __nv_bfloat16* __restrict__ h1, __nv_bfloat16* __restrict__ l1,
                                  __nv_bfloat16* __restrict__ h2, __nv_bfloat16* __restrict__ l2,
                                  __nv_bfloat16* __restrict__ h3, __nv_bfloat16* __restrict__ l3,
                                  const float* __restrict__ x,
                                  uint32_t* __restrict__ hiX, uint32_t* __restrict__ loX,
                                  int* __restrict__ cnt) {
    const int S1 = IN_DIM * HID_DIM;
    const int S2 = S1 + HID_DIM * HID_DIM;
    int i = blockIdx.x * blockDim.x + threadIdx.x;
    if (i < WTOT) {
        if (i < S1) {
            int k = i / HID_DIM, n = i % HID_DIM;
            float v = W1[i];
            __nv_bfloat16 h = __float2bfloat16(v);
            h1[(size_t)n * IN_DIM + k] = h;
            l1[(size_t)n * IN_DIM + k] = __float2bfloat16(v - __bfloat162float(h));
        } else if (i < S2) {
            int j = i - S1;
            int k = j / HID_DIM, n = j % HID_DIM;
            float v = W2[j];
            __nv_bfloat16 h = __float2bfloat16(v);
            h2[(size_t)n * HID_DIM + k] = h;
            l2[(size_t)n * HID_DIM + k] = __float2bfloat16(v - __bfloat162float(h));
        } else {
            int j = i - S2;
            int k = j / OUT_DIM, n = j % OUT_DIM;
            float v = W3[j];
            __nv_bfloat16 h = __float2bfloat16(v);
            h3[(size_t)n * HID_DIM + k] = h;
            l3[(size_t)n * HID_DIM + k] = __float2bfloat16(v - __bfloat162float(h));
        }
    } else if (i < WTOT + XTOT4) {
        int j = i - WTOT;
        float4 v = ((const float4*)x)[j];
        uint32_t h0, l0, h1u, l1u;
        split2(v.x, v.y, h0, l0);
        split2(v.z, v.w, h1u, l1u);
        hiX[2 * j] = h0; hiX[2 * j + 1] = h1u;
        loX[2 * j] = l0; loX[2 * j + 1] = l1u;
    } else if (i < WTOT + XTOT4 + N_NODES) {
        cnt[i - WTOT - XTOT4] = 0;
    }
}

// ---------------- preprocessing kernels ----------------
__global__ void count_edges_kernel(const int* __restrict__ ei, int* cnt, int E) {
    int e = blockIdx.x * blockDim.x + threadIdx.x;
    if (e < E) {
        int d = ei[E + e];
        if (d >= 0 && d < N_NODES) atomicAdd(&cnt[d], 1);
    }
}

__global__ void scan_kernel(const int* __restrict__ cnt, int* rowptr, int* cursor,
                            float* dinv, int n) {
    __shared__ int ssum[1024];
    int tid = threadIdx.x;
    const int CH = (n + 1023) / 1024;
    int base = tid * CH;
    int local = 0;
    for (int i = 0; i < CH; i++) {
        int idx = base + i;
        if (idx < n) local += cnt[idx];
    }
    ssum[tid] = local;
    __syncthreads();
    for (int off = 1; off < 1024; off <<= 1) {
        int v = ssum[tid];
        int add = (tid >= off) ? ssum[tid - off] : 0;
        __syncthreads();
        ssum[tid] = v + add;
        __syncthreads();
    }
    int run = (tid > 0) ? ssum[tid - 1] : 0;
    for (int i = 0; i < CH; i++) {
        int idx = base + i;
        if (idx < n) {
            rowptr[idx] = run;
            cursor[idx] = run;
            int c = cnt[idx];
            run += c;
            dinv[idx] = rsqrtf((float)c + 1.0f);
        }
    }
    if (tid == 1023) rowptr[n] = run;
}

__global__ void fill_csr_kernel(const int* __restrict__ ei, int* cursor,
                                int* colsrc, int E) {
    int e = blockIdx.x * blockDim.x + threadIdx.x;
    if (e < E) {
        int s = ei[e];
        int d = ei[E + e];
        if (d >= 0 && d < N_NODES) {
            int p = atomicAdd(&cursor[d], 1);
            colsrc[p] = s;
        }
    }
}

// ---------------- mma.sync bf16 GEMM, XOR-swizzled smem, 2 CTAs/SM ----------------
// Phase-reordered mainloop: per ks-step run hh-all, lh-all, hl-all (16 independent
// MMAs per phase) to eliminate RAW accumulator chains on the HMMA pipe.
#define TILE_B 8192
#define STAGE_B (4 * TILE_B)       // 32768
#define GEMM_SMEM (2 * STAGE_B)    // 65536

__device__ __forceinline__ uint32_t swz(uint32_t row, uint32_t c) {
    return ((row >> 1) << 7) | ((((((row & 1u) << 2) | c)) ^ ((row >> 1) & 3u)) << 4);
}
__device__ __forceinline__ void cp16(uint32_t dst, const void* src, bool pred) {
    int sz = pred ? 16 : 0;
    asm volatile("cp.async.cg.shared.global [%0], [%1], 16, %2;"
                 :: "r"(dst), "l"(src), "r"(sz) : "memory");
}
__device__ __forceinline__ void mma_bf16(float c[4], const uint32_t a[4], const uint32_t b[2]) {
    asm volatile(
        "mma.sync.aligned.m16n8k16.row.col.f32.bf16.bf16.f32 "
        "{%0,%1,%2,%3}, {%4,%5,%6,%7}, {%8,%9}, {%0,%1,%2,%3};"
        : "+f"(c[0]), "+f"(c[1]), "+f"(c[2]), "+f"(c[3])
        : "r"(a[0]), "r"(a[1]), "r"(a[2]), "r"(a[3]), "r"(b[0]), "r"(b[1]));
}
__device__ __forceinline__ void ldsm_x4(uint32_t r[4], uint32_t addr) {
    asm volatile("ldmatrix.sync.aligned.m8n8.x4.shared.b16 {%0,%1,%2,%3}, [%4];"
                 : "=r"(r[0]), "=r"(r[1]), "=r"(r[2]), "=r"(r[3]) : "r"(addr));
}
__device__ __forceinline__ void ldsm_x2(uint32_t r[2], uint32_t addr) {
    asm volatile("ldmatrix.sync.aligned.m8n8.x2.shared.b16 {%0,%1}, [%2];"
                 : "=r"(r[0]), "=r"(r[1]) : "r"(addr));
}
__device__ __forceinline__ uint32_t smem_u32p(const void* p) {
    uint32_t a;
    asm("{ .reg .u64 t; cvta.to.shared.u64 t, %1; cvt.u32.u64 %0, t; }" : "=r"(a) : "l"(p));
    return a;
}

__global__ __launch_bounds__(256, 2) void gemm_mma_kernel(
    const uint32_t* __restrict__ Ahi2, const uint32_t* __restrict__ Alo2,
    const uint32_t* __restrict__ Bhi2, const uint32_t* __restrict__ Blo2,
    const float* __restrict__ dinv, float* __restrict__ C,
    int Mm, int Nn, int Kk)
{
    extern __shared__ __align__(16) uint32_t sm[];
    const uint32_t sb = smem_u32p(sm);

    const int tid = threadIdx.x;
    const int wid = tid >> 5;
    const int lid = tid & 31;
    const int g = lid >> 2;
    const int t = lid & 3;
    const int row0 = blockIdx.y * 128;
    const int col0 = blockIdx.x * 128;
    const int m0 = (wid & 1) * 64;
    const int n0 = (wid >> 1) * 32;
    const int Ku = Kk >> 1;

    float acc[4][4][4];
#pragma unroll
    for (int mt = 0; mt < 4; mt++)
#pragma unroll
        for (int nt = 0; nt < 4; nt++)
#pragma unroll
            for (int i = 0; i < 4; i++) acc[mt][nt][i] = 0.0f;

    auto load_tiles = [&](int buf, int kt) {
        const int k0u = kt * 16;
#pragma unroll
        for (int it = 0; it < 8; it++) {
            int c = it * 256 + tid;
            int tile = c >> 9;
            int r = (c >> 2) & 127;
            int ch = c & 3;
            uint32_t dst = sb + (uint32_t)(buf * STAGE_B + tile * TILE_B) + swz((uint32_t)r, (uint32_t)ch);
            const uint32_t* src;
            bool p = true;
            if (tile < 2) {
                int gr = row0 + r;
                p = gr < Mm;
                int gra = p ? gr : 0;
                src = (tile == 0 ? Ahi2 : Alo2) + (size_t)gra * Ku + k0u + ch * 4;
            } else {
                int gn = col0 + r;
                src = (tile == 2 ? Bhi2 : Blo2) + (size_t)gn * Ku + k0u + ch * 4;
            }
            cp16(dst, src, p);
        }
        asm volatile("cp.async.commit_group;" ::: "memory");
    };

    const int nkt = Kk / 32;
    load_tiles(0, 0);

    const uint32_t aR = (uint32_t)(m0 + (lid & 15));
    const uint32_t aC = (uint32_t)(lid >> 4);          // + ks*2
    const uint32_t bR = (uint32_t)(n0 + (lid & 7));
    const uint32_t bC = (uint32_t)((lid >> 3) & 1);    // + ks*2

    for (int kt = 0; kt < nkt; kt++) {
        int buf = kt & 1;
        if (kt + 1 < nkt) {
            load_tiles(buf ^ 1, kt + 1);
            asm volatile("cp.async.wait_group 1;" ::: "memory");
        } else {
            asm volatile("cp.async.wait_group 0;" ::: "memory");
        }
        __syncthreads();

        const uint32_t base = sb + (uint32_t)(buf * STAGE_B);

#pragma unroll
        for (int ks = 0; ks < 2; ks++) {
            uint32_t ah[4][4];
            uint32_t bq[4][2];
            // load A-hi and B-hi fragments
#pragma unroll
            for (int mt = 0; mt < 4; mt++)
                ldsm_x4(ah[mt], base + swz(aR + mt * 16, aC + ks * 2));
#pragma unroll
            for (int nt = 0; nt < 4; nt++)
                ldsm_x2(bq[nt], base + 2 * TILE_B + swz(bR + nt * 8, bC + ks * 2));

            // phase 1: hi*hi — 16 independent MMAs
#pragma unroll
            for (int mt = 0; mt < 4; mt++)
#pragma unroll
                for (int nt = 0; nt < 4; nt++)
                    mma_bf16(acc[mt][nt], ah[mt], bq[nt]);

            // phase 2: lo*hi — load A-lo, 16 independent MMAs
            {
                uint32_t al[4][4];
#pragma unroll
                for (int mt = 0; mt < 4; mt++)
                    ldsm_x4(al[mt], base + TILE_B + swz(aR + mt * 16, aC + ks * 2));
#pragma unroll
                for (int mt = 0; mt < 4; mt++)
#pragma unroll
                    for (int nt = 0; nt < 4; nt++)
                        mma_bf16(acc[mt][nt], al[mt], bq[nt]);
            }

            // phase 3: hi*lo — overwrite B fragments with B-lo, 16 independent MMAs
#pragma unroll
            for (int nt = 0; nt < 4; nt++)
                ldsm_x2(bq[nt], base + 3 * TILE_B + swz(bR + nt * 8, bC + ks * 2));
#pragma unroll
            for (int mt = 0; mt < 4; mt++)
#pragma unroll
                for (int nt = 0; nt < 4; nt++)
                    mma_bf16(acc[mt][nt], ah[mt], bq[nt]);
        }
        __syncthreads();
    }

    // ---- epilogue: direct register -> gmem with dinv row scale ----
#pragma unroll
    for (int mt = 0; mt < 4; mt++) {
        int r0 = row0 + m0 + mt * 16 + g;
        int r1 = r0 + 8;
        float s0 = (r0 < Mm) ? dinv[r0] : 0.0f;
        float s1 = (r1 < Mm) ? dinv[r1] : 0.0f;
#pragma unroll
        for (int nt = 0; nt < 4; nt++) {
            int cn = col0 + n0 + nt * 8 + t * 2;
            if (r0 < Mm) {
                float2 v0 = make_float2(acc[mt][nt][0] * s0, acc[mt][nt][1] * s0);
                *(float2*)(C + (size_t)r0 * Nn + cn) = v0;
            }
            if (r1 < Mm) {
                float2 v1 = make_float2(acc[mt][nt][2] * s1, acc[mt][nt][3] * s1);
                *(float2*)(C + (size_t)r1 * Nn + cn) = v1;
            }
        }
    }
}

// ---------------- aggregation: v = tanh/id( dinv[i]*(G[i] + sum G[src]) + b ) ----------------
template <int APPLY_TANH, int SPLIT_OUT>
__global__ void agg_kernel_t(const float* __restrict__ G,
                             const float* __restrict__ bias,
                             const float* __restrict__ dinv,
                             const int* __restrict__ rowptr,
                             const int* __restrict__ colsrc,
                             float* __restrict__ outF,
                             uint2* __restrict__ outHi,
                             uint2* __restrict__ outLo,
                             int F4)
{
    int i = blockIdx.x;
    int t = threadIdx.x;
    const float4* G4 = (const float4*)G;

    float4 acc = __ldg(&G4[(size_t)i * F4 + t]);

    int e   = rowptr[i];
    int end = rowptr[i + 1];
    for (; e + 4 <= end; e += 4) {
        int s0 = __ldg(&colsrc[e + 0]);
        int s1 = __ldg(&colsrc[e + 1]);
        int s2 = __ldg(&colsrc[e + 2]);
        int s3 = __ldg(&colsrc[e + 3]);
        float4 v0 = __ldg(&G4[(size_t)s0 * F4 + t]);
        float4 v1 = __ldg(&G4[(size_t)s1 * F4 + t]);
        float4 v2 = __ldg(&G4[(size_t)s2 * F4 + t]);
        float4 v3 = __ldg(&G4[(size_t)s3 * F4 + t]);
        acc.x += v0.x + v1.x + v2.x + v3.x;
        acc.y += v0.y + v1.y + v2.y + v3.y;
        acc.z += v0.z + v1.z + v2.z + v3.z;
        acc.w += v0.w + v1.w + v2.w + v3.w;
    }
    for (; e < end; ++e) {
        int s = __ldg(&colsrc[e]);
        float4 v = __ldg(&G4[(size_t)s * F4 + t]);
        acc.x += v.x; acc.y += v.y; acc.z += v.z; acc.w += v.w;
    }

    float di = dinv[i];
    float4 bb = ((const float4*)bias)[t];
    float4 r;
    r.x = fmaf(acc.x, di, bb.x);
    r.y = fmaf(acc.y, di, bb.y);
    r.z = fmaf(acc.z, di, bb.z);
    r.w = fmaf(acc.w, di, bb.w);
    if (APPLY_TANH) {
        r.x = tanhf(r.x); r.y = tanhf(r.y);
        r.z = tanhf(r.z); r.w = tanhf(r.w);
    }
    if (SPLIT_OUT) {
        uint32_t h0, l0, h1, l1;
        split2(r.x, r.y, h0, l0);
        split2(r.z, r.w, h1, l1);
        outHi[(size_t)i * F4 + t] = make_uint2(h0, h1);
        outLo[(size_t)i * F4 + t] = make_uint2(l0, l1);
    } else {
        ((float4*)outF)[(size_t)i * F4 + t] = r;
    }
}

// ---------------- launch ----------------
extern "C" void kernel_launch(void* const* d_in, const int* in_sizes, int n_in,
                              void* d_out, int out_size) {
    const float* x  = (const float*)d_in[0];
    const float* W1 = (const float*)d_in[1];
    const float* b1 = (const float*)d_in[2];
    const float* W2 = (const float*)d_in[3];
    const float* b2 = (const float*)d_in[4];
    const float* W3 = (const float*)d_in[5];
    const float* b3 = (const float*)d_in[6];
    const int*   ei = (const int*)d_in[7];    // int32 edge_index [2, E]
    float* out = (float*)d_out;

    const int N = N_NODES;
    const int E = in_sizes[7] / 2;

    float *bufA, *dinv;
    int *cnt, *rowptr, *cursor, *colsrc;
    __nv_bfloat16 *hiA, *loA, *w1h, *w1l, *w2h, *w2l, *w3h, *w3l;
    cudaGetSymbolAddress((void**)&bufA,   g_bufA);
    cudaGetSymbolAddress((void**)&dinv,   g_dinv);
    cudaGetSymbolAddress((void**)&cnt,    g_cnt);
    cudaGetSymbolAddress((void**)&rowptr, g_rowptr);
    cudaGetSymbolAddress((void**)&cursor, g_cursor);
    cudaGetSymbolAddress((void**)&colsrc, g_colsrc);
    cudaGetSymbolAddress((void**)&hiA,    g_hiA);
    cudaGetSymbolAddress((void**)&loA,    g_loA);
    cudaGetSymbolAddress((void**)&w1h,    g_W1tHi);
    cudaGetSymbolAddress((void**)&w1l,    g_W1tLo);
    cudaGetSymbolAddress((void**)&w2h,    g_W2tHi);
    cudaGetSymbolAddress((void**)&w2l,    g_W2tLo);
    cudaGetSymbolAddress((void**)&w3h,    g_W3tHi);
    cudaGetSymbolAddress((void**)&w3l,    g_W3tLo);

    static bool attr_set = false;
    if (!attr_set) {
        cudaFuncSetAttribute(gemm_mma_kernel, cudaFuncAttributeMaxDynamicSharedMemorySize, GEMM_SMEM);
        attr_set = true;
    }

    // --- fused one-shot prep (W splits, x split, cnt zero) ---
    {
        int total = WTOT + XTOT4 + N;
        fused_prep_kernel<<<(total + 255) / 256, 256>>>(W1, W2, W3, w1h, w1l, w2h, w2l, w3h, w3l,
                                                        x, (uint32_t*)hiA, (uint32_t*)loA, cnt);
    }
    // --- CSR by dst ---
    count_edges_kernel<<<(E + 255) / 256, 256>>>(ei, cnt, E);
    scan_kernel<<<1, 1024>>>(cnt, rowptr, cursor, dinv, N);
    fill_csr_kernel<<<(E + 255) / 256, 256>>>(ei, cursor, colsrc, E);

    const int MT = (N + 127) / 128;

    // --- layer 1 ---
    {
        dim3 grid(HID_DIM / 128, MT);
        gemm_mma_kernel<<<grid, 256, GEMM_SMEM>>>((uint32_t*)hiA, (uint32_t*)loA,
                                                  (uint32_t*)w1h, (uint32_t*)w1l,
                                                  dinv, bufA, N, HID_DIM, IN_DIM);
        agg_kernel_t<1, 1><<<N, HID_DIM / 4>>>(bufA, b1, dinv, rowptr, colsrc,
                                               nullptr, (uint2*)hiA, (uint2*)loA, HID_DIM / 4);
    }
    // --- layer 2 ---
    {
        dim3 grid(HID_DIM / 128, MT);
        gemm_mma_kernel<<<grid, 256, GEMM_SMEM>>>((uint32_t*)hiA, (uint32_t*)loA,
                                                  (uint32_t*)w2h, (uint32_t*)w2l,
                                                  dinv, bufA, N, HID_DIM, HID_DIM);
        agg_kernel_t<1, 1><<<N, HID_DIM / 4>>>(bufA, b2, dinv, rowptr, colsrc,
                                               nullptr, (uint2*)hiA, (uint2*)loA, HID_DIM / 4);
    }
    // --- layer 3 ---
    {
        dim3 grid(OUT_DIM / 128, MT);
        gemm_mma_kernel<<<grid, 256, GEMM_SMEM>>>((uint32_t*)hiA, (uint32_t*)loA,
                                                  (uint32_t*)w3h, (uint32_t*)w3l,
                                                  dinv, bufA, N, OUT_DIM, HID_DIM);
        agg_kernel_t<0, 0><<<N, OUT_DIM / 4>>>(bufA, b3, dinv, rowptr, colsrc,
                                               out, nullptr, nullptr, OUT_DIM / 4);
    }
}

// round 8
// speedup vs baseline: 2.7490x; 1.2320x over previous
#include <cuda_runtime.h>
#include <cuda_fp16.h>
#include <math.h>
#include <stdint.h>

// ---------------- problem constants ----------------
#define N_NODES 10000
#define N_EDGES 160000
#define IN_DIM  256
#define HID_DIM 512
#define OUT_DIM 256

// ---------------- device scratch (no allocs allowed) ----------------
__device__ float  g_bufA[N_NODES * HID_DIM];     // GEMM output (scaled)
__device__ __half g_hiA[N_NODES * HID_DIM];      // activation hi split (fp16)
__device__ __half g_loA[N_NODES * HID_DIM];      // activation lo split (fp16)
__device__ __half g_W1t[IN_DIM * HID_DIM];       // W^T fp16
__device__ __half g_W2t[HID_DIM * HID_DIM];
__device__ __half g_W3t[HID_DIM * OUT_DIM];
__device__ float  g_dinv[N_NODES];
__device__ int    g_cnt[N_NODES];
__device__ int    g_rowptr[N_NODES + 1];
__device__ int    g_cursor[N_NODES];
__device__ int    g_colsrc[N_EDGES];

// ---------------- split helper (fp16 hi/lo) ----------------
__device__ __forceinline__ void split2h(float a, float b, uint32_t& hi, uint32_t& lo) {
    __half ha = __float2half_rn(a);
    __half hb = __float2half_rn(b);
    __half la = __float2half_rn(a - __half2float(ha));
    __half lb = __float2half_rn(b - __half2float(hb));
    hi = (uint32_t)__half_as_ushort(ha) | ((uint32_t)__half_as_ushort(hb) << 16);
    lo = (uint32_t)__half_as_ushort(la) | ((uint32_t)__half_as_ushort(lb) << 16);
}

// ---------------- fused one-shot prep: W1/W2/W3 -> W^T fp16, x -> fp16 hi/lo, cnt zero ----------------
#define WTOT (IN_DIM * HID_DIM + HID_DIM * HID_DIM + HID_DIM * OUT_DIM)   // 524288
#define XTOT4 (N_NODES * IN_DIM / 4)                                     // 640000
__global__ void fused_prep_kernel(const float* __restrict__ W1, const float* __restrict__ W2,
                                  const float* __restrict__ W3,
                                  __half* __restrict__ w1t, __half* __restrict__ w2t,
                                  __half* __restrict__ w3t,
                                  const float* __restrict__ x,
                                  uint32_t* __restrict__ hiX, uint32_t* __restrict__ loX,
                                  int* __restrict__ cnt) {
    const int S1 = IN_DIM * HID_DIM;
    const int S2 = S1 + HID_DIM * HID_DIM;
    int i = blockIdx.x * blockDim.x + threadIdx.x;
    if (i < WTOT) {
        if (i < S1) {
            int k = i / HID_DIM, n = i % HID_DIM;
            w1t[(size_t)n * IN_DIM + k] = __float2half_rn(W1[i]);
        } else if (i < S2) {
            int j = i - S1;
            int k = j / HID_DIM, n = j % HID_DIM;
            w2t[(size_t)n * HID_DIM + k] = __float2half_rn(W2[j]);
        } else {
            int j = i - S2;
            int k = j / OUT_DIM, n = j % OUT_DIM;
            w3t[(size_t)n * HID_DIM + k] = __float2half_rn(W3[j]);
        }
    } else if (i < WTOT + XTOT4) {
        int j = i - WTOT;
        float4 v = ((const float4*)x)[j];
        uint32_t h0, l0, h1u, l1u;
        split2h(v.x, v.y, h0, l0);
        split2h(v.z, v.w, h1u, l1u);
        hiX[2 * j] = h0; hiX[2 * j + 1] = h1u;
        loX[2 * j] = l0; loX[2 * j + 1] = l1u;
    } else if (i < WTOT + XTOT4 + N_NODES) {
        cnt[i - WTOT - XTOT4] = 0;
    }
}

// ---------------- preprocessing kernels (2 edges/thread) ----------------
__global__ void count_edges_kernel(const int* __restrict__ ei, int* cnt, int E) {
    int e = (blockIdx.x * blockDim.x + threadIdx.x) * 2;
    if (e < E) {
        int d = ei[E + e];
        if (d >= 0 && d < N_NODES) atomicAdd(&cnt[d], 1);
    }
    if (e + 1 < E) {
        int d = ei[E + e + 1];
        if (d >= 0 && d < N_NODES) atomicAdd(&cnt[d], 1);
    }
}

__global__ void scan_kernel(const int* __restrict__ cnt, int* rowptr, int* cursor,
                            float* dinv, int n) {
    __shared__ int ssum[1024];
    int tid = threadIdx.x;
    const int CH = (n + 1023) / 1024;
    int base = tid * CH;
    int local = 0;
    for (int i = 0; i < CH; i++) {
        int idx = base + i;
        if (idx < n) local += cnt[idx];
    }
    ssum[tid] = local;
    __syncthreads();
    for (int off = 1; off < 1024; off <<= 1) {
        int v = ssum[tid];
        int add = (tid >= off) ? ssum[tid - off] : 0;
        __syncthreads();
        ssum[tid] = v + add;
        __syncthreads();
    }
    int run = (tid > 0) ? ssum[tid - 1] : 0;
    for (int i = 0; i < CH; i++) {
        int idx = base + i;
        if (idx < n) {
            rowptr[idx] = run;
            cursor[idx] = run;
            int c = cnt[idx];
            run += c;
            dinv[idx] = rsqrtf((float)c + 1.0f);
        }
    }
    if (tid == 1023) rowptr[n] = run;
}

__global__ void fill_csr_kernel(const int* __restrict__ ei, int* cursor,
                                int* colsrc, int E) {
    int e = (blockIdx.x * blockDim.x + threadIdx.x) * 2;
    if (e < E) {
        int s = ei[e];
        int d = ei[E + e];
        if (d >= 0 && d < N_NODES) {
            int p = atomicAdd(&cursor[d], 1);
            colsrc[p] = s;
        }
    }
    if (e + 1 < E) {
        int s = ei[e + 1];
        int d = ei[E + e + 1];
        if (d >= 0 && d < N_NODES) {
            int p = atomicAdd(&cursor[d], 1);
            colsrc[p] = s;
        }
    }
}

// ---------------- mma.sync fp16 GEMM, 2-pass x-split, XOR-swizzled smem, 2 CTAs/SM ----------------
// C[r][c] = dinv[r] * sum_k (x_hi + x_lo)[r][k] * W16t[c][k], fp32 accum.
// CTA tile 128x128; 8 warps (2M x 4N), warp tile 64x32; BK=32 double-buffered cp.async.
// 3 tiles per stage (A-hi, A-lo, B), 8KB each -> 24KB/stage, 48KB total.
#define TILE_B 8192
#define STAGE_B (3 * TILE_B)       // 24576
#define GEMM_SMEM (2 * STAGE_B)    // 49152

__device__ __forceinline__ uint32_t swz(uint32_t row, uint32_t c) {
    return ((row >> 1) << 7) | ((((((row & 1u) << 2) | c)) ^ ((row >> 1) & 3u)) << 4);
}
__device__ __forceinline__ void cp16(uint32_t dst, const void* src, bool pred) {
    int sz = pred ? 16 : 0;
    asm volatile("cp.async.cg.shared.global [%0], [%1], 16, %2;"
                 :: "r"(dst), "l"(src), "r"(sz) : "memory");
}
__device__ __forceinline__ void mma_f16(float c[4], const uint32_t a[4], const uint32_t b[2]) {
    asm volatile(
        "mma.sync.aligned.m16n8k16.row.col.f32.f16.f16.f32 "
        "{%0,%1,%2,%3}, {%4,%5,%6,%7}, {%8,%9}, {%0,%1,%2,%3};"
        : "+f"(c[0]), "+f"(c[1]), "+f"(c[2]), "+f"(c[3])
        : "r"(a[0]), "r"(a[1]), "r"(a[2]), "r"(a[3]), "r"(b[0]), "r"(b[1]));
}
__device__ __forceinline__ void ldsm_x4(uint32_t r[4], uint32_t addr) {
    asm volatile("ldmatrix.sync.aligned.m8n8.x4.shared.b16 {%0,%1,%2,%3}, [%4];"
                 : "=r"(r[0]), "=r"(r[1]), "=r"(r[2]), "=r"(r[3]) : "r"(addr));
}
__device__ __forceinline__ void ldsm_x2(uint32_t r[2], uint32_t addr) {
    asm volatile("ldmatrix.sync.aligned.m8n8.x2.shared.b16 {%0,%1}, [%2];"
                 : "=r"(r[0]), "=r"(r[1]) : "r"(addr));
}
__device__ __forceinline__ uint32_t smem_u32p(const void* p) {
    uint32_t a;
    asm("{ .reg .u64 t; cvta.to.shared.u64 t, %1; cvt.u32.u64 %0, t; }" : "=r"(a) : "l"(p));
    return a;
}

__global__ __launch_bounds__(256, 2) void gemm_mma_kernel(
    const uint32_t* __restrict__ Ahi2, const uint32_t* __restrict__ Alo2,
    const uint32_t* __restrict__ B2,
    const float* __restrict__ dinv, float* __restrict__ C,
    int Mm, int Nn, int Kk)
{
    extern __shared__ __align__(16) uint32_t sm[];
    const uint32_t sb = smem_u32p(sm);

    const int tid = threadIdx.x;
    const int wid = tid >> 5;
    const int lid = tid & 31;
    const int g = lid >> 2;
    const int t = lid & 3;
    const int row0 = blockIdx.y * 128;
    const int col0 = blockIdx.x * 128;
    const int m0 = (wid & 1) * 64;
    const int n0 = (wid >> 1) * 32;
    const int Ku = Kk >> 1;

    float acc[4][4][4];
#pragma unroll
    for (int mt = 0; mt < 4; mt++)
#pragma unroll
        for (int nt = 0; nt < 4; nt++)
#pragma unroll
            for (int i = 0; i < 4; i++) acc[mt][nt][i] = 0.0f;

    // loader: 3 tiles x 128 rows x 4 chunks = 1536 chunks, 256 threads -> 6 iters
    auto load_tiles = [&](int buf, int kt) {
        const int k0u = kt * 16;
#pragma unroll
        for (int it = 0; it < 6; it++) {
            int c = it * 256 + tid;
            int tile = c >> 9;
            int r = (c >> 2) & 127;
            int ch = c & 3;
            uint32_t dst = sb + (uint32_t)(buf * STAGE_B + tile * TILE_B) + swz((uint32_t)r, (uint32_t)ch);
            const uint32_t* src;
            bool p = true;
            if (tile < 2) {
                int gr = row0 + r;
                p = gr < Mm;
                int gra = p ? gr : 0;
                src = (tile == 0 ? Ahi2 : Alo2) + (size_t)gra * Ku + k0u + ch * 4;
            } else {
                int gn = col0 + r;
                src = B2 + (size_t)gn * Ku + k0u + ch * 4;
            }
            cp16(dst, src, p);
        }
        asm volatile("cp.async.commit_group;" ::: "memory");
    };

    const int nkt = Kk / 32;
    load_tiles(0, 0);

    const uint32_t aR = (uint32_t)(m0 + (lid & 15));
    const uint32_t aC = (uint32_t)(lid >> 4);          // + ks*2
    const uint32_t bR = (uint32_t)(n0 + (lid & 7));
    const uint32_t bC = (uint32_t)((lid >> 3) & 1);    // + ks*2

    for (int kt = 0; kt < nkt; kt++) {
        int buf = kt & 1;
        if (kt + 1 < nkt) {
            load_tiles(buf ^ 1, kt + 1);
            asm volatile("cp.async.wait_group 1;" ::: "memory");
        } else {
            asm volatile("cp.async.wait_group 0;" ::: "memory");
        }
        __syncthreads();

        const uint32_t base = sb + (uint32_t)(buf * STAGE_B);

#pragma unroll
        for (int ks = 0; ks < 2; ks++) {
            uint32_t ah[4][4];
            uint32_t bq[4][2];
#pragma unroll
            for (int mt = 0; mt < 4; mt++)
                ldsm_x4(ah[mt], base + swz(aR + mt * 16, aC + ks * 2));
#pragma unroll
            for (int nt = 0; nt < 4; nt++)
                ldsm_x2(bq[nt], base + 2 * TILE_B + swz(bR + nt * 8, bC + ks * 2));

            // pass 1: x_hi * W — 16 independent MMAs
#pragma unroll
            for (int mt = 0; mt < 4; mt++)
#pragma unroll
                for (int nt = 0; nt < 4; nt++)
                    mma_f16(acc[mt][nt], ah[mt], bq[nt]);

            // pass 2: x_lo * W — 16 independent MMAs
            {
                uint32_t al[4][4];
#pragma unroll
                for (int mt = 0; mt < 4; mt++)
                    ldsm_x4(al[mt], base + TILE_B + swz(aR + mt * 16, aC + ks * 2));
#pragma unroll
                for (int mt = 0; mt < 4; mt++)
#pragma unroll
                    for (int nt = 0; nt < 4; nt++)
                        mma_f16(acc[mt][nt], al[mt], bq[nt]);
            }
        }
        __syncthreads();
    }

    // ---- epilogue: direct register -> gmem with dinv row scale ----
#pragma unroll
    for (int mt = 0; mt < 4; mt++) {
        int r0 = row0 + m0 + mt * 16 + g;
        int r1 = r0 + 8;
        float s0 = (r0 < Mm) ? dinv[r0] : 0.0f;
        float s1 = (r1 < Mm) ? dinv[r1] : 0.0f;
#pragma unroll
        for (int nt = 0; nt < 4; nt++) {
            int cn = col0 + n0 + nt * 8 + t * 2;
            if (r0 < Mm) {
                float2 v0 = make_float2(acc[mt][nt][0] * s0, acc[mt][nt][1] * s0);
                *(float2*)(C + (size_t)r0 * Nn + cn) = v0;
            }
            if (r1 < Mm) {
                float2 v1 = make_float2(acc[mt][nt][2] * s1, acc[mt][nt][3] * s1);
                *(float2*)(C + (size_t)r1 * Nn + cn) = v1;
            }
        }
    }
}

// ---------------- aggregation: v = tanh/id( dinv[i]*(G[i] + sum G[src]) + b ) ----------------
template <int APPLY_TANH, int SPLIT_OUT>
__global__ void agg_kernel_t(const float* __restrict__ G,
                             const float* __restrict__ bias,
                             const float* __restrict__ dinv,
                             const int* __restrict__ rowptr,
                             const int* __restrict__ colsrc,
                             float* __restrict__ outF,
                             uint2* __restrict__ outHi,
                             uint2* __restrict__ outLo,
                             int F4)
{
    int i = blockIdx.x;
    int t = threadIdx.x;
    const float4* G4 = (const float4*)G;

    float4 acc = __ldg(&G4[(size_t)i * F4 + t]);

    int e   = rowptr[i];
    int end = rowptr[i + 1];
    for (; e + 4 <= end; e += 4) {
        int s0 = __ldg(&colsrc[e + 0]);
        int s1 = __ldg(&colsrc[e + 1]);
        int s2 = __ldg(&colsrc[e + 2]);
        int s3 = __ldg(&colsrc[e + 3]);
        float4 v0 = __ldg(&G4[(size_t)s0 * F4 + t]);
        float4 v1 = __ldg(&G4[(size_t)s1 * F4 + t]);
        float4 v2 = __ldg(&G4[(size_t)s2 * F4 + t]);
        float4 v3 = __ldg(&G4[(size_t)s3 * F4 + t]);
        acc.x += v0.x + v1.x + v2.x + v3.x;
        acc.y += v0.y + v1.y + v2.y + v3.y;
        acc.z += v0.z + v1.z + v2.z + v3.z;
        acc.w += v0.w + v1.w + v2.w + v3.w;
    }
    for (; e < end; ++e) {
        int s = __ldg(&colsrc[e]);
        float4 v = __ldg(&G4[(size_t)s * F4 + t]);
        acc.x += v.x; acc.y += v.y; acc.z += v.z; acc.w += v.w;
    }

    float di = dinv[i];
    float4 bb = ((const float4*)bias)[t];
    float4 r;
    r.x = fmaf(acc.x, di, bb.x);
    r.y = fmaf(acc.y, di, bb.y);
    r.z = fmaf(acc.z, di, bb.z);
    r.w = fmaf(acc.w, di, bb.w);
    if (APPLY_TANH) {
        r.x = tanhf(r.x); r.y = tanhf(r.y);
        r.z = tanhf(r.z); r.w = tanhf(r.w);
    }
    if (SPLIT_OUT) {
        uint32_t h0, l0, h1, l1;
        split2h(r.x, r.y, h0, l0);
        split2h(r.z, r.w, h1, l1);
        outHi[(size_t)i * F4 + t] = make_uint2(h0, h1);
        outLo[(size_t)i * F4 + t] = make_uint2(l0, l1);
    } else {
        ((float4*)outF)[(size_t)i * F4 + t] = r;
    }
}

// ---------------- launch ----------------
extern "C" void kernel_launch(void* const* d_in, const int* in_sizes, int n_in,
                              void* d_out, int out_size) {
    const float* x  = (const float*)d_in[0];
    const float* W1 = (const float*)d_in[1];
    const float* b1 = (const float*)d_in[2];
    const float* W2 = (const float*)d_in[3];
    const float* b2 = (const float*)d_in[4];
    const float* W3 = (const float*)d_in[5];
    const float* b3 = (const float*)d_in[6];
    const int*   ei = (const int*)d_in[7];    // int32 edge_index [2, E]
    float* out = (float*)d_out;

    const int N = N_NODES;
    const int E = in_sizes[7] / 2;

    float *bufA, *dinv;
    int *cnt, *rowptr, *cursor, *colsrc;
    __half *hiA, *loA, *w1t, *w2t, *w3t;
    cudaGetSymbolAddress((void**)&bufA,   g_bufA);
    cudaGetSymbolAddress((void**)&dinv,   g_dinv);
    cudaGetSymbolAddress((void**)&cnt,    g_cnt);
    cudaGetSymbolAddress((void**)&rowptr, g_rowptr);
    cudaGetSymbolAddress((void**)&cursor, g_cursor);
    cudaGetSymbolAddress((void**)&colsrc, g_colsrc);
    cudaGetSymbolAddress((void**)&hiA,    g_hiA);
    cudaGetSymbolAddress((void**)&loA,    g_loA);
    cudaGetSymbolAddress((void**)&w1t,    g_W1t);
    cudaGetSymbolAddress((void**)&w2t,    g_W2t);
    cudaGetSymbolAddress((void**)&w3t,    g_W3t);

    static bool attr_set = false;
    if (!attr_set) {
        cudaFuncSetAttribute(gemm_mma_kernel, cudaFuncAttributeMaxDynamicSharedMemorySize, GEMM_SMEM);
        attr_set = true;
    }

    // --- fused one-shot prep (W fp16 transpose, x fp16 split, cnt zero) ---
    {
        int total = WTOT + XTOT4 + N;
        fused_prep_kernel<<<(total + 255) / 256, 256>>>(W1, W2, W3, w1t, w2t, w3t,
                                                        x, (uint32_t*)hiA, (uint32_t*)loA, cnt);
    }
    // --- CSR by dst ---
    count_edges_kernel<<<(E / 2 + 255) / 256, 256>>>(ei, cnt, E);
    scan_kernel<<<1, 1024>>>(cnt, rowptr, cursor, dinv, N);
    fill_csr_kernel<<<(E / 2 + 255) / 256, 256>>>(ei, cursor, colsrc, E);

    const int MT = (N + 127) / 128;

    // --- layer 1 ---
    {
        dim3 grid(HID_DIM / 128, MT);
        gemm_mma_kernel<<<grid, 256, GEMM_SMEM>>>((uint32_t*)hiA, (uint32_t*)loA,
                                                  (uint32_t*)w1t,
                                                  dinv, bufA, N, HID_DIM, IN_DIM);
        agg_kernel_t<1, 1><<<N, HID_DIM / 4>>>(bufA, b1, dinv, rowptr, colsrc,
                                               nullptr, (uint2*)hiA, (uint2*)loA, HID_DIM / 4);
    }
    // --- layer 2 ---
    {
        dim3 grid(HID_DIM / 128, MT);
        gemm_mma_kernel<<<grid, 256, GEMM_SMEM>>>((uint32_t*)hiA, (uint32_t*)loA,
                                                  (uint32_t*)w2t,
                                                  dinv, bufA, N, HID_DIM, HID_DIM);
        agg_kernel_t<1, 1><<<N, HID_DIM / 4>>>(bufA, b2, dinv, rowptr, colsrc,
                                               nullptr, (uint2*)hiA, (uint2*)loA, HID_DIM / 4);
    }
    // --- layer 3 ---
    {
        dim3 grid(OUT_DIM / 128, MT);
        gemm_mma_kernel<<<grid, 256, GEMM_SMEM>>>((uint32_t*)hiA, (uint32_t*)loA,
                                                  (uint32_t*)w3t,
                                                  dinv, bufA, N, OUT_DIM, HID_DIM);
        agg_kernel_t<0, 0><<<N, OUT_DIM / 4>>>(bufA, b3, dinv, rowptr, colsrc,
                                               out, nullptr, nullptr, OUT_DIM / 4);
    }
}

// round 9
// speedup vs baseline: 2.7731x; 1.0088x over previous
#include <cuda_runtime.h>
#include <cuda_fp16.h>
#include <math.h>
#include <stdint.h>

// ---------------- problem constants ----------------
#define N_NODES 10000
#define N_EDGES 160000
#define IN_DIM  256
#define HID_DIM 512
#define OUT_DIM 256

// ---------------- device scratch (no allocs allowed) ----------------
__device__ float  g_bufA[N_NODES * HID_DIM];     // GEMM fp32 output (scaled)
__device__ __half g_hiA[N_NODES * HID_DIM];      // split pair A
__device__ __half g_loA[N_NODES * HID_DIM];
__device__ __half g_hiB[N_NODES * HID_DIM];      // split pair B
__device__ __half g_loB[N_NODES * HID_DIM];
__device__ __half g_W1t[IN_DIM * HID_DIM];       // W^T fp16
__device__ __half g_W2t[HID_DIM * HID_DIM];
__device__ __half g_W3t[HID_DIM * OUT_DIM];
__device__ float  g_dinv[N_NODES];
__device__ int    g_cnt[N_NODES];
__device__ int    g_rowptr[N_NODES + 1];
__device__ int    g_cursor[N_NODES];
__device__ int    g_colsrc[N_EDGES];

// ---------------- split helper (fp16 hi/lo) ----------------
__device__ __forceinline__ void split2h(float a, float b, uint32_t& hi, uint32_t& lo) {
    __half ha = __float2half_rn(a);
    __half hb = __float2half_rn(b);
    __half la = __float2half_rn(a - __half2float(ha));
    __half lb = __float2half_rn(b - __half2float(hb));
    hi = (uint32_t)__half_as_ushort(ha) | ((uint32_t)__half_as_ushort(hb) << 16);
    lo = (uint32_t)__half_as_ushort(la) | ((uint32_t)__half_as_ushort(lb) << 16);
}

// ---------------- fused one-shot prep: W1/W2/W3 -> W^T fp16, cnt zero ----------------
#define WTOT (IN_DIM * HID_DIM + HID_DIM * HID_DIM + HID_DIM * OUT_DIM)   // 524288
__global__ void fused_prep_kernel(const float* __restrict__ W1, const float* __restrict__ W2,
                                  const float* __restrict__ W3,
                                  __half* __restrict__ w1t, __half* __restrict__ w2t,
                                  __half* __restrict__ w3t,
                                  int* __restrict__ cnt) {
    const int S1 = IN_DIM * HID_DIM;
    const int S2 = S1 + HID_DIM * HID_DIM;
    int i = blockIdx.x * blockDim.x + threadIdx.x;
    if (i < WTOT) {
        if (i < S1) {
            int k = i / HID_DIM, n = i % HID_DIM;
            w1t[(size_t)n * IN_DIM + k] = __float2half_rn(W1[i]);
        } else if (i < S2) {
            int j = i - S1;
            int k = j / HID_DIM, n = j % HID_DIM;
            w2t[(size_t)n * HID_DIM + k] = __float2half_rn(W2[j]);
        } else {
            int j = i - S2;
            int k = j / OUT_DIM, n = j % OUT_DIM;
            w3t[(size_t)n * HID_DIM + k] = __float2half_rn(W3[j]);
        }
    } else if (i < WTOT + N_NODES) {
        cnt[i - WTOT] = 0;
    }
}

// ---------------- preprocessing kernels (2 edges/thread) ----------------
__global__ void count_edges_kernel(const int* __restrict__ ei, int* cnt, int E) {
    int e = (blockIdx.x * blockDim.x + threadIdx.x) * 2;
    if (e < E) {
        int d = ei[E + e];
        if (d >= 0 && d < N_NODES) atomicAdd(&cnt[d], 1);
    }
    if (e + 1 < E) {
        int d = ei[E + e + 1];
        if (d >= 0 && d < N_NODES) atomicAdd(&cnt[d], 1);
    }
}

__global__ void scan_kernel(const int* __restrict__ cnt, int* rowptr, int* cursor,
                            float* dinv, int n) {
    __shared__ int ssum[1024];
    int tid = threadIdx.x;
    const int CH = (n + 1023) / 1024;
    int base = tid * CH;
    int local = 0;
    for (int i = 0; i < CH; i++) {
        int idx = base + i;
        if (idx < n) local += cnt[idx];
    }
    ssum[tid] = local;
    __syncthreads();
    for (int off = 1; off < 1024; off <<= 1) {
        int v = ssum[tid];
        int add = (tid >= off) ? ssum[tid - off] : 0;
        __syncthreads();
        ssum[tid] = v + add;
        __syncthreads();
    }
    int run = (tid > 0) ? ssum[tid - 1] : 0;
    for (int i = 0; i < CH; i++) {
        int idx = base + i;
        if (idx < n) {
            rowptr[idx] = run;
            cursor[idx] = run;
            int c = cnt[idx];
            run += c;
            dinv[idx] = rsqrtf((float)c + 1.0f);
        }
    }
    if (tid == 1023) rowptr[n] = run;
}

__global__ void fill_csr_kernel(const int* __restrict__ ei, int* cursor,
                                int* colsrc, int E) {
    int e = (blockIdx.x * blockDim.x + threadIdx.x) * 2;
    if (e < E) {
        int s = ei[e];
        int d = ei[E + e];
        if (d >= 0 && d < N_NODES) {
            int p = atomicAdd(&cursor[d], 1);
            colsrc[p] = s;
        }
    }
    if (e + 1 < E) {
        int s = ei[e + 1];
        int d = ei[E + e + 1];
        if (d >= 0 && d < N_NODES) {
            int p = atomicAdd(&cursor[d], 1);
            colsrc[p] = s;
        }
    }
}

// ---------------- layer-1 pre-aggregation on raw x (256-wide gather) ----------------
// out_i = dinv_i * ( x_i*dinv_i + sum_src x_src*dinv_src ), split to fp16 hi/lo
__global__ void agg_x_split_kernel(const float* __restrict__ X,
                                   const float* __restrict__ dinv,
                                   const int* __restrict__ rowptr,
                                   const int* __restrict__ colsrc,
                                   uint2* __restrict__ outHi,
                                   uint2* __restrict__ outLo)
{
    const int F4 = IN_DIM / 4;   // 64
    int i = blockIdx.x;
    int t = threadIdx.x;
    const float4* X4 = (const float4*)X;

    float di = dinv[i];
    float4 xv = __ldg(&X4[(size_t)i * F4 + t]);
    float4 acc;
    acc.x = xv.x * di; acc.y = xv.y * di; acc.z = xv.z * di; acc.w = xv.w * di;

    int e   = rowptr[i];
    int end = rowptr[i + 1];
    for (; e + 2 <= end; e += 2) {
        int s0 = __ldg(&colsrc[e + 0]);
        int s1 = __ldg(&colsrc[e + 1]);
        float w0 = __ldg(&dinv[s0]);
        float w1 = __ldg(&dinv[s1]);
        float4 v0 = __ldg(&X4[(size_t)s0 * F4 + t]);
        float4 v1 = __ldg(&X4[(size_t)s1 * F4 + t]);
        acc.x += v0.x * w0 + v1.x * w1;
        acc.y += v0.y * w0 + v1.y * w1;
        acc.z += v0.z * w0 + v1.z * w1;
        acc.w += v0.w * w0 + v1.w * w1;
    }
    for (; e < end; ++e) {
        int s = __ldg(&colsrc[e]);
        float w = __ldg(&dinv[s]);
        float4 v = __ldg(&X4[(size_t)s * F4 + t]);
        acc.x += v.x * w; acc.y += v.y * w; acc.z += v.z * w; acc.w += v.w * w;
    }

    uint32_t h0, l0, h1, l1;
    split2h(acc.x * di, acc.y * di, h0, l0);
    split2h(acc.z * di, acc.w * di, h1, l1);
    outHi[(size_t)i * F4 + t] = make_uint2(h0, h1);
    outLo[(size_t)i * F4 + t] = make_uint2(l0, l1);
}

// ---------------- mma.sync fp16 GEMM, 2-pass x-split, XOR-swizzled smem, 2 CTAs/SM ----------------
// EPI_TANH=0: C[r][c] = dinv[r] * acc  (fp32 out)
// EPI_TANH=1: v = tanh(acc + bias[c]); split -> outHi/outLo (fp16 pairs)
#define TILE_B 8192
#define STAGE_B (3 * TILE_B)       // 24576
#define GEMM_SMEM (2 * STAGE_B)    // 49152

__device__ __forceinline__ uint32_t swz(uint32_t row, uint32_t c) {
    return ((row >> 1) << 7) | ((((((row & 1u) << 2) | c)) ^ ((row >> 1) & 3u)) << 4);
}
__device__ __forceinline__ void cp16(uint32_t dst, const void* src, bool pred) {
    int sz = pred ? 16 : 0;
    asm volatile("cp.async.cg.shared.global [%0], [%1], 16, %2;"
                 :: "r"(dst), "l"(src), "r"(sz) : "memory");
}
__device__ __forceinline__ void mma_f16(float c[4], const uint32_t a[4], const uint32_t b[2]) {
    asm volatile(
        "mma.sync.aligned.m16n8k16.row.col.f32.f16.f16.f32 "
        "{%0,%1,%2,%3}, {%4,%5,%6,%7}, {%8,%9}, {%0,%1,%2,%3};"
        : "+f"(c[0]), "+f"(c[1]), "+f"(c[2]), "+f"(c[3])
        : "r"(a[0]), "r"(a[1]), "r"(a[2]), "r"(a[3]), "r"(b[0]), "r"(b[1]));
}
__device__ __forceinline__ void ldsm_x4(uint32_t r[4], uint32_t addr) {
    asm volatile("ldmatrix.sync.aligned.m8n8.x4.shared.b16 {%0,%1,%2,%3}, [%4];"
                 : "=r"(r[0]), "=r"(r[1]), "=r"(r[2]), "=r"(r[3]) : "r"(addr));
}
__device__ __forceinline__ void ldsm_x2(uint32_t r[2], uint32_t addr) {
    asm volatile("ldmatrix.sync.aligned.m8n8.x2.shared.b16 {%0,%1}, [%2];"
                 : "=r"(r[0]), "=r"(r[1]) : "r"(addr));
}
__device__ __forceinline__ uint32_t smem_u32p(const void* p) {
    uint32_t a;
    asm("{ .reg .u64 t; cvta.to.shared.u64 t, %1; cvt.u32.u64 %0, t; }" : "=r"(a) : "l"(p));
    return a;
}

template <int EPI_TANH>
__global__ __launch_bounds__(256, 2) void gemm_mma_kernel(
    const uint32_t* __restrict__ Ahi2, const uint32_t* __restrict__ Alo2,
    const uint32_t* __restrict__ B2,
    const float* __restrict__ dinv, const float* __restrict__ bias,
    float* __restrict__ C, uint32_t* __restrict__ outHi, uint32_t* __restrict__ outLo,
    int Mm, int Nn, int Kk)
{
    extern __shared__ __align__(16) uint32_t sm[];
    const uint32_t sb = smem_u32p(sm);

    const int tid = threadIdx.x;
    const int wid = tid >> 5;
    const int lid = tid & 31;
    const int g = lid >> 2;
    const int t = lid & 3;
    const int row0 = blockIdx.y * 128;
    const int col0 = blockIdx.x * 128;
    const int m0 = (wid & 1) * 64;
    const int n0 = (wid >> 1) * 32;
    const int Ku = Kk >> 1;

    float acc[4][4][4];
#pragma unroll
    for (int mt = 0; mt < 4; mt++)
#pragma unroll
        for (int nt = 0; nt < 4; nt++)
#pragma unroll
            for (int i = 0; i < 4; i++) acc[mt][nt][i] = 0.0f;

    auto load_tiles = [&](int buf, int kt) {
        const int k0u = kt * 16;
#pragma unroll
        for (int it = 0; it < 6; it++) {
            int c = it * 256 + tid;
            int tile = c >> 9;
            int r = (c >> 2) & 127;
            int ch = c & 3;
            uint32_t dst = sb + (uint32_t)(buf * STAGE_B + tile * TILE_B) + swz((uint32_t)r, (uint32_t)ch);
            const uint32_t* src;
            bool p = true;
            if (tile < 2) {
                int gr = row0 + r;
                p = gr < Mm;
                int gra = p ? gr : 0;
                src = (tile == 0 ? Ahi2 : Alo2) + (size_t)gra * Ku + k0u + ch * 4;
            } else {
                int gn = col0 + r;
                src = B2 + (size_t)gn * Ku + k0u + ch * 4;
            }
            cp16(dst, src, p);
        }
        asm volatile("cp.async.commit_group;" ::: "memory");
    };

    const int nkt = Kk / 32;
    load_tiles(0, 0);

    const uint32_t aR = (uint32_t)(m0 + (lid & 15));
    const uint32_t aC = (uint32_t)(lid >> 4);
    const uint32_t bR = (uint32_t)(n0 + (lid & 7));
    const uint32_t bC = (uint32_t)((lid >> 3) & 1);

    for (int kt = 0; kt < nkt; kt++) {
        int buf = kt & 1;
        if (kt + 1 < nkt) {
            load_tiles(buf ^ 1, kt + 1);
            asm volatile("cp.async.wait_group 1;" ::: "memory");
        } else {
            asm volatile("cp.async.wait_group 0;" ::: "memory");
        }
        __syncthreads();

        const uint32_t base = sb + (uint32_t)(buf * STAGE_B);

#pragma unroll
        for (int ks = 0; ks < 2; ks++) {
            uint32_t ah[4][4];
            uint32_t bq[4][2];
#pragma unroll
            for (int mt = 0; mt < 4; mt++)
                ldsm_x4(ah[mt], base + swz(aR + mt * 16, aC + ks * 2));
#pragma unroll
            for (int nt = 0; nt < 4; nt++)
                ldsm_x2(bq[nt], base + 2 * TILE_B + swz(bR + nt * 8, bC + ks * 2));

#pragma unroll
            for (int mt = 0; mt < 4; mt++)
#pragma unroll
                for (int nt = 0; nt < 4; nt++)
                    mma_f16(acc[mt][nt], ah[mt], bq[nt]);

            {
                uint32_t al[4][4];
#pragma unroll
                for (int mt = 0; mt < 4; mt++)
                    ldsm_x4(al[mt], base + TILE_B + swz(aR + mt * 16, aC + ks * 2));
#pragma unroll
                for (int mt = 0; mt < 4; mt++)
#pragma unroll
                    for (int nt = 0; nt < 4; nt++)
                        mma_f16(acc[mt][nt], al[mt], bq[nt]);
            }
        }
        __syncthreads();
    }

    // ---- epilogue ----
#pragma unroll
    for (int mt = 0; mt < 4; mt++) {
        int r0 = row0 + m0 + mt * 16 + g;
        int r1 = r0 + 8;
        if (EPI_TANH) {
#pragma unroll
            for (int nt = 0; nt < 4; nt++) {
                int cn = col0 + n0 + nt * 8 + t * 2;
                float bx = bias[cn], by = bias[cn + 1];
                if (r0 < Mm) {
                    uint32_t h, l;
                    split2h(tanhf(acc[mt][nt][0] + bx), tanhf(acc[mt][nt][1] + by), h, l);
                    outHi[((size_t)r0 * Nn + cn) >> 1] = h;
                    outLo[((size_t)r0 * Nn + cn) >> 1] = l;
                }
                if (r1 < Mm) {
                    uint32_t h, l;
                    split2h(tanhf(acc[mt][nt][2] + bx), tanhf(acc[mt][nt][3] + by), h, l);
                    outHi[((size_t)r1 * Nn + cn) >> 1] = h;
                    outLo[((size_t)r1 * Nn + cn) >> 1] = l;
                }
            }
        } else {
            float s0 = (r0 < Mm) ? dinv[r0] : 0.0f;
            float s1 = (r1 < Mm) ? dinv[r1] : 0.0f;
#pragma unroll
            for (int nt = 0; nt < 4; nt++) {
                int cn = col0 + n0 + nt * 8 + t * 2;
                if (r0 < Mm) {
                    float2 v0 = make_float2(acc[mt][nt][0] * s0, acc[mt][nt][1] * s0);
                    *(float2*)(C + (size_t)r0 * Nn + cn) = v0;
                }
                if (r1 < Mm) {
                    float2 v1 = make_float2(acc[mt][nt][2] * s1, acc[mt][nt][3] * s1);
                    *(float2*)(C + (size_t)r1 * Nn + cn) = v1;
                }
            }
        }
    }
}

// ---------------- aggregation: v = tanh/id( dinv[i]*(G[i] + sum G[src]) + b ) ----------------
template <int APPLY_TANH, int SPLIT_OUT>
__global__ void agg_kernel_t(const float* __restrict__ G,
                             const float* __restrict__ bias,
                             const float* __restrict__ dinv,
                             const int* __restrict__ rowptr,
                             const int* __restrict__ colsrc,
                             float* __restrict__ outF,
                             uint2* __restrict__ outHi,
                             uint2* __restrict__ outLo,
                             int F4)
{
    int i = blockIdx.x;
    int t = threadIdx.x;
    const float4* G4 = (const float4*)G;

    float4 acc = __ldg(&G4[(size_t)i * F4 + t]);

    int e   = rowptr[i];
    int end = rowptr[i + 1];
    for (; e + 4 <= end; e += 4) {
        int s0 = __ldg(&colsrc[e + 0]);
        int s1 = __ldg(&colsrc[e + 1]);
        int s2 = __ldg(&colsrc[e + 2]);
        int s3 = __ldg(&colsrc[e + 3]);
        float4 v0 = __ldg(&G4[(size_t)s0 * F4 + t]);
        float4 v1 = __ldg(&G4[(size_t)s1 * F4 + t]);
        float4 v2 = __ldg(&G4[(size_t)s2 * F4 + t]);
        float4 v3 = __ldg(&G4[(size_t)s3 * F4 + t]);
        acc.x += v0.x + v1.x + v2.x + v3.x;
        acc.y += v0.y + v1.y + v2.y + v3.y;
        acc.z += v0.z + v1.z + v2.z + v3.z;
        acc.w += v0.w + v1.w + v2.w + v3.w;
    }
    for (; e < end; ++e) {
        int s = __ldg(&colsrc[e]);
        float4 v = __ldg(&G4[(size_t)s * F4 + t]);
        acc.x += v.x; acc.y += v.y; acc.z += v.z; acc.w += v.w;
    }

    float di = dinv[i];
    float4 bb = ((const float4*)bias)[t];
    float4 r;
    r.x = fmaf(acc.x, di, bb.x);
    r.y = fmaf(acc.y, di, bb.y);
    r.z = fmaf(acc.z, di, bb.z);
    r.w = fmaf(acc.w, di, bb.w);
    if (APPLY_TANH) {
        r.x = tanhf(r.x); r.y = tanhf(r.y);
        r.z = tanhf(r.z); r.w = tanhf(r.w);
    }
    if (SPLIT_OUT) {
        uint32_t h0, l0, h1, l1;
        split2h(r.x, r.y, h0, l0);
        split2h(r.z, r.w, h1, l1);
        outHi[(size_t)i * F4 + t] = make_uint2(h0, h1);
        outLo[(size_t)i * F4 + t] = make_uint2(l0, l1);
    } else {
        ((float4*)outF)[(size_t)i * F4 + t] = r;
    }
}

// ---------------- launch ----------------
extern "C" void kernel_launch(void* const* d_in, const int* in_sizes, int n_in,
                              void* d_out, int out_size) {
    const float* x  = (const float*)d_in[0];
    const float* W1 = (const float*)d_in[1];
    const float* b1 = (const float*)d_in[2];
    const float* W2 = (const float*)d_in[3];
    const float* b2 = (const float*)d_in[4];
    const float* W3 = (const float*)d_in[5];
    const float* b3 = (const float*)d_in[6];
    const int*   ei = (const int*)d_in[7];    // int32 edge_index [2, E]
    float* out = (float*)d_out;

    const int N = N_NODES;
    const int E = in_sizes[7] / 2;

    float *bufA, *dinv;
    int *cnt, *rowptr, *cursor, *colsrc;
    __half *hiA, *loA, *hiB, *loB, *w1t, *w2t, *w3t;
    cudaGetSymbolAddress((void**)&bufA,   g_bufA);
    cudaGetSymbolAddress((void**)&dinv,   g_dinv);
    cudaGetSymbolAddress((void**)&cnt,    g_cnt);
    cudaGetSymbolAddress((void**)&rowptr, g_rowptr);
    cudaGetSymbolAddress((void**)&cursor, g_cursor);
    cudaGetSymbolAddress((void**)&colsrc, g_colsrc);
    cudaGetSymbolAddress((void**)&hiA,    g_hiA);
    cudaGetSymbolAddress((void**)&loA,    g_loA);
    cudaGetSymbolAddress((void**)&hiB,    g_hiB);
    cudaGetSymbolAddress((void**)&loB,    g_loB);
    cudaGetSymbolAddress((void**)&w1t,    g_W1t);
    cudaGetSymbolAddress((void**)&w2t,    g_W2t);
    cudaGetSymbolAddress((void**)&w3t,    g_W3t);

    static bool attr_set = false;
    if (!attr_set) {
        cudaFuncSetAttribute(gemm_mma_kernel<0>, cudaFuncAttributeMaxDynamicSharedMemorySize, GEMM_SMEM);
        cudaFuncSetAttribute(gemm_mma_kernel<1>, cudaFuncAttributeMaxDynamicSharedMemorySize, GEMM_SMEM);
        attr_set = true;
    }

    // --- fused one-shot prep (W fp16 transpose, cnt zero) ---
    fused_prep_kernel<<<(WTOT + N + 255) / 256, 256>>>(W1, W2, W3, w1t, w2t, w3t, cnt);
    // --- CSR by dst ---
    count_edges_kernel<<<(E / 2 + 255) / 256, 256>>>(ei, cnt, E);
    scan_kernel<<<1, 1024>>>(cnt, rowptr, cursor, dinv, N);
    fill_csr_kernel<<<(E / 2 + 255) / 256, 256>>>(ei, cursor, colsrc, E);

    const int MT = (N + 127) / 128;

    // --- layer 1: aggregate x first (256-wide), then GEMM with tanh+split epilogue ---
    agg_x_split_kernel<<<N, IN_DIM / 4>>>(x, dinv, rowptr, colsrc, (uint2*)hiA, (uint2*)loA);
    {
        dim3 grid(HID_DIM / 128, MT);
        gemm_mma_kernel<1><<<grid, 256, GEMM_SMEM>>>((uint32_t*)hiA, (uint32_t*)loA,
                                                     (uint32_t*)w1t, nullptr, b1,
                                                     nullptr, (uint32_t*)hiB, (uint32_t*)loB,
                                                     N, HID_DIM, IN_DIM);
    }
    // --- layer 2: GEMM (dinv epi) -> agg(tanh+split) ---
    {
        dim3 grid(HID_DIM / 128, MT);
        gemm_mma_kernel<0><<<grid, 256, GEMM_SMEM>>>((uint32_t*)hiB, (uint32_t*)loB,
                                                     (uint32_t*)w2t, dinv, nullptr,
                                                     bufA, nullptr, nullptr,
                                                     N, HID_DIM, HID_DIM);
        agg_kernel_t<1, 1><<<N, HID_DIM / 4>>>(bufA, b2, dinv, rowptr, colsrc,
                                               nullptr, (uint2*)hiA, (uint2*)loA, HID_DIM / 4);
    }
    // --- layer 3: GEMM (dinv epi, 256-wide) -> agg(bias, fp32 out) ---
    {
        dim3 grid(OUT_DIM / 128, MT);
        gemm_mma_kernel<0><<<grid, 256, GEMM_SMEM>>>((uint32_t*)hiA, (uint32_t*)loA,
                                                     (uint32_t*)w3t, dinv, nullptr,
                                                     bufA, nullptr, nullptr,
                                                     N, OUT_DIM, HID_DIM);
        agg_kernel_t<0, 0><<<N, OUT_DIM / 4>>>(bufA, b3, dinv, rowptr, colsrc,
                                               out, nullptr, nullptr, OUT_DIM / 4);
    }
}

// round 10
// speedup vs baseline: 2.8613x; 1.0318x over previous
#include <cuda_runtime.h>
#include <cuda_fp16.h>
#include <math.h>
#include <stdint.h>

// ---------------- problem constants ----------------
#define N_NODES 10000
#define N_EDGES 160000
#define IN_DIM  256
#define HID_DIM 512
#define OUT_DIM 256

// ---------------- device scratch (no allocs allowed) ----------------
__device__ __half g_bufH[N_NODES * HID_DIM];     // GEMM fp16 output (scaled)
__device__ __half g_hiA[N_NODES * HID_DIM];      // split pair A
__device__ __half g_loA[N_NODES * HID_DIM];
__device__ __half g_hiB[N_NODES * HID_DIM];      // split pair B
__device__ __half g_loB[N_NODES * HID_DIM];
__device__ __half g_W1t[IN_DIM * HID_DIM];       // W^T fp16
__device__ __half g_W2t[HID_DIM * HID_DIM];
__device__ __half g_W3t[HID_DIM * OUT_DIM];
__device__ float  g_dinv[N_NODES];
__device__ int    g_cnt[N_NODES];
__device__ int    g_rowptr[N_NODES + 1];
__device__ int    g_cursor[N_NODES];
__device__ int    g_colsrc[N_EDGES];

// ---------------- split helper (fp16 hi/lo) ----------------
__device__ __forceinline__ void split2h(float a, float b, uint32_t& hi, uint32_t& lo) {
    __half ha = __float2half_rn(a);
    __half hb = __float2half_rn(b);
    __half la = __float2half_rn(a - __half2float(ha));
    __half lb = __float2half_rn(b - __half2float(hb));
    hi = (uint32_t)__half_as_ushort(ha) | ((uint32_t)__half_as_ushort(hb) << 16);
    lo = (uint32_t)__half_as_ushort(la) | ((uint32_t)__half_as_ushort(lb) << 16);
}
__device__ __forceinline__ uint32_t pack2h(float a, float b) {
    __half2 h = __floats2half2_rn(a, b);
    return *reinterpret_cast<uint32_t*>(&h);
}

// ---------------- fused one-shot prep: W1/W2/W3 -> W^T fp16, cnt zero ----------------
#define WTOT (IN_DIM * HID_DIM + HID_DIM * HID_DIM + HID_DIM * OUT_DIM)   // 524288
__global__ void fused_prep_kernel(const float* __restrict__ W1, const float* __restrict__ W2,
                                  const float* __restrict__ W3,
                                  __half* __restrict__ w1t, __half* __restrict__ w2t,
                                  __half* __restrict__ w3t,
                                  int* __restrict__ cnt) {
    const int S1 = IN_DIM * HID_DIM;
    const int S2 = S1 + HID_DIM * HID_DIM;
    int i = blockIdx.x * blockDim.x + threadIdx.x;
    if (i < WTOT) {
        if (i < S1) {
            int k = i / HID_DIM, n = i % HID_DIM;
            w1t[(size_t)n * IN_DIM + k] = __float2half_rn(W1[i]);
        } else if (i < S2) {
            int j = i - S1;
            int k = j / HID_DIM, n = j % HID_DIM;
            w2t[(size_t)n * HID_DIM + k] = __float2half_rn(W2[j]);
        } else {
            int j = i - S2;
            int k = j / OUT_DIM, n = j % OUT_DIM;
            w3t[(size_t)n * HID_DIM + k] = __float2half_rn(W3[j]);
        }
    } else if (i < WTOT + N_NODES) {
        cnt[i - WTOT] = 0;
    }
}

// ---------------- preprocessing kernels (2 edges/thread) ----------------
__global__ void count_edges_kernel(const int* __restrict__ ei, int* cnt, int E) {
    int e = (blockIdx.x * blockDim.x + threadIdx.x) * 2;
    if (e < E) {
        int d = ei[E + e];
        if (d >= 0 && d < N_NODES) atomicAdd(&cnt[d], 1);
    }
    if (e + 1 < E) {
        int d = ei[E + e + 1];
        if (d >= 0 && d < N_NODES) atomicAdd(&cnt[d], 1);
    }
}

__global__ void scan_kernel(const int* __restrict__ cnt, int* rowptr, int* cursor,
                            float* dinv, int n) {
    __shared__ int ssum[1024];
    int tid = threadIdx.x;
    const int CH = (n + 1023) / 1024;
    int base = tid * CH;
    int local = 0;
    for (int i = 0; i < CH; i++) {
        int idx = base + i;
        if (idx < n) local += cnt[idx];
    }
    ssum[tid] = local;
    __syncthreads();
    for (int off = 1; off < 1024; off <<= 1) {
        int v = ssum[tid];
        int add = (tid >= off) ? ssum[tid - off] : 0;
        __syncthreads();
        ssum[tid] = v + add;
        __syncthreads();
    }
    int run = (tid > 0) ? ssum[tid - 1] : 0;
    for (int i = 0; i < CH; i++) {
        int idx = base + i;
        if (idx < n) {
            rowptr[idx] = run;
            cursor[idx] = run;
            int c = cnt[idx];
            run += c;
            dinv[idx] = rsqrtf((float)c + 1.0f);
        }
    }
    if (tid == 1023) rowptr[n] = run;
}

__global__ void fill_csr_kernel(const int* __restrict__ ei, int* cursor,
                                int* colsrc, int E) {
    int e = (blockIdx.x * blockDim.x + threadIdx.x) * 2;
    if (e < E) {
        int s = ei[e];
        int d = ei[E + e];
        if (d >= 0 && d < N_NODES) {
            int p = atomicAdd(&cursor[d], 1);
            colsrc[p] = s;
        }
    }
    if (e + 1 < E) {
        int s = ei[e + 1];
        int d = ei[E + e + 1];
        if (d >= 0 && d < N_NODES) {
            int p = atomicAdd(&cursor[d], 1);
            colsrc[p] = s;
        }
    }
}

// ---------------- layer-1 pre-aggregation on raw x (256-wide gather) ----------------
__global__ void agg_x_split_kernel(const float* __restrict__ X,
                                   const float* __restrict__ dinv,
                                   const int* __restrict__ rowptr,
                                   const int* __restrict__ colsrc,
                                   uint2* __restrict__ outHi,
                                   uint2* __restrict__ outLo)
{
    const int F4 = IN_DIM / 4;   // 64
    int i = blockIdx.x;
    int t = threadIdx.x;
    const float4* X4 = (const float4*)X;

    float di = dinv[i];
    float4 xv = __ldg(&X4[(size_t)i * F4 + t]);
    float4 acc;
    acc.x = xv.x * di; acc.y = xv.y * di; acc.z = xv.z * di; acc.w = xv.w * di;

    int e   = rowptr[i];
    int end = rowptr[i + 1];
    for (; e + 2 <= end; e += 2) {
        int s0 = __ldg(&colsrc[e + 0]);
        int s1 = __ldg(&colsrc[e + 1]);
        float w0 = __ldg(&dinv[s0]);
        float w1 = __ldg(&dinv[s1]);
        float4 v0 = __ldg(&X4[(size_t)s0 * F4 + t]);
        float4 v1 = __ldg(&X4[(size_t)s1 * F4 + t]);
        acc.x += v0.x * w0 + v1.x * w1;
        acc.y += v0.y * w0 + v1.y * w1;
        acc.z += v0.z * w0 + v1.z * w1;
        acc.w += v0.w * w0 + v1.w * w1;
    }
    for (; e < end; ++e) {
        int s = __ldg(&colsrc[e]);
        float w = __ldg(&dinv[s]);
        float4 v = __ldg(&X4[(size_t)s * F4 + t]);
        acc.x += v.x * w; acc.y += v.y * w; acc.z += v.z * w; acc.w += v.w * w;
    }

    uint32_t h0, l0, h1, l1;
    split2h(acc.x * di, acc.y * di, h0, l0);
    split2h(acc.z * di, acc.w * di, h1, l1);
    outHi[(size_t)i * F4 + t] = make_uint2(h0, h1);
    outLo[(size_t)i * F4 + t] = make_uint2(l0, l1);
}

// ---------------- mma.sync fp16 GEMM, 2-pass x-split, XOR-swizzled smem, 2 CTAs/SM ----------------
// EPI_TANH=0: Ch[r][c] = half( dinv[r] * acc )   (packed half2 out)
// EPI_TANH=1: v = tanh(acc + bias[c]); split -> outHi/outLo (fp16 pairs)
#define TILE_B 8192
#define STAGE_B (3 * TILE_B)       // 24576
#define GEMM_SMEM (2 * STAGE_B)    // 49152

__device__ __forceinline__ uint32_t swz(uint32_t row, uint32_t c) {
    return ((row >> 1) << 7) | ((((((row & 1u) << 2) | c)) ^ ((row >> 1) & 3u)) << 4);
}
__device__ __forceinline__ void cp16(uint32_t dst, const void* src, bool pred) {
    int sz = pred ? 16 : 0;
    asm volatile("cp.async.cg.shared.global [%0], [%1], 16, %2;"
                 :: "r"(dst), "l"(src), "r"(sz) : "memory");
}
__device__ __forceinline__ void mma_f16(float c[4], const uint32_t a[4], const uint32_t b[2]) {
    asm volatile(
        "mma.sync.aligned.m16n8k16.row.col.f32.f16.f16.f32 "
        "{%0,%1,%2,%3}, {%4,%5,%6,%7}, {%8,%9}, {%0,%1,%2,%3};"
        : "+f"(c[0]), "+f"(c[1]), "+f"(c[2]), "+f"(c[3])
        : "r"(a[0]), "r"(a[1]), "r"(a[2]), "r"(a[3]), "r"(b[0]), "r"(b[1]));
}
__device__ __forceinline__ void ldsm_x4(uint32_t r[4], uint32_t addr) {
    asm volatile("ldmatrix.sync.aligned.m8n8.x4.shared.b16 {%0,%1,%2,%3}, [%4];"
                 : "=r"(r[0]), "=r"(r[1]), "=r"(r[2]), "=r"(r[3]) : "r"(addr));
}
__device__ __forceinline__ void ldsm_x2(uint32_t r[2], uint32_t addr) {
    asm volatile("ldmatrix.sync.aligned.m8n8.x2.shared.b16 {%0,%1}, [%2];"
                 : "=r"(r[0]), "=r"(r[1]) : "r"(addr));
}
__device__ __forceinline__ uint32_t smem_u32p(const void* p) {
    uint32_t a;
    asm("{ .reg .u64 t; cvta.to.shared.u64 t, %1; cvt.u32.u64 %0, t; }" : "=r"(a) : "l"(p));
    return a;
}

template <int EPI_TANH>
__global__ __launch_bounds__(256, 2) void gemm_mma_kernel(
    const uint32_t* __restrict__ Ahi2, const uint32_t* __restrict__ Alo2,
    const uint32_t* __restrict__ B2,
    const float* __restrict__ dinv, const float* __restrict__ bias,
    uint32_t* __restrict__ Ch, uint32_t* __restrict__ outHi, uint32_t* __restrict__ outLo,
    int Mm, int Nn, int Kk)
{
    extern __shared__ __align__(16) uint32_t sm[];
    const uint32_t sb = smem_u32p(sm);

    const int tid = threadIdx.x;
    const int wid = tid >> 5;
    const int lid = tid & 31;
    const int g = lid >> 2;
    const int t = lid & 3;
    const int row0 = blockIdx.y * 128;
    const int col0 = blockIdx.x * 128;
    const int m0 = (wid & 1) * 64;
    const int n0 = (wid >> 1) * 32;
    const int Ku = Kk >> 1;

    float acc[4][4][4];
#pragma unroll
    for (int mt = 0; mt < 4; mt++)
#pragma unroll
        for (int nt = 0; nt < 4; nt++)
#pragma unroll
            for (int i = 0; i < 4; i++) acc[mt][nt][i] = 0.0f;

    auto load_tiles = [&](int buf, int kt) {
        const int k0u = kt * 16;
#pragma unroll
        for (int it = 0; it < 6; it++) {
            int c = it * 256 + tid;
            int tile = c >> 9;
            int r = (c >> 2) & 127;
            int ch = c & 3;
            uint32_t dst = sb + (uint32_t)(buf * STAGE_B + tile * TILE_B) + swz((uint32_t)r, (uint32_t)ch);
            const uint32_t* src;
            bool p = true;
            if (tile < 2) {
                int gr = row0 + r;
                p = gr < Mm;
                int gra = p ? gr : 0;
                src = (tile == 0 ? Ahi2 : Alo2) + (size_t)gra * Ku + k0u + ch * 4;
            } else {
                int gn = col0 + r;
                src = B2 + (size_t)gn * Ku + k0u + ch * 4;
            }
            cp16(dst, src, p);
        }
        asm volatile("cp.async.commit_group;" ::: "memory");
    };

    const int nkt = Kk / 32;
    load_tiles(0, 0);

    const uint32_t aR = (uint32_t)(m0 + (lid & 15));
    const uint32_t aC = (uint32_t)(lid >> 4);
    const uint32_t bR = (uint32_t)(n0 + (lid & 7));
    const uint32_t bC = (uint32_t)((lid >> 3) & 1);

    for (int kt = 0; kt < nkt; kt++) {
        int buf = kt & 1;
        if (kt + 1 < nkt) {
            load_tiles(buf ^ 1, kt + 1);
            asm volatile("cp.async.wait_group 1;" ::: "memory");
        } else {
            asm volatile("cp.async.wait_group 0;" ::: "memory");
        }
        __syncthreads();

        const uint32_t base = sb + (uint32_t)(buf * STAGE_B);

#pragma unroll
        for (int ks = 0; ks < 2; ks++) {
            uint32_t ah[4][4];
            uint32_t bq[4][2];
#pragma unroll
            for (int mt = 0; mt < 4; mt++)
                ldsm_x4(ah[mt], base + swz(aR + mt * 16, aC + ks * 2));
#pragma unroll
            for (int nt = 0; nt < 4; nt++)
                ldsm_x2(bq[nt], base + 2 * TILE_B + swz(bR + nt * 8, bC + ks * 2));

#pragma unroll
            for (int mt = 0; mt < 4; mt++)
#pragma unroll
                for (int nt = 0; nt < 4; nt++)
                    mma_f16(acc[mt][nt], ah[mt], bq[nt]);

            {
                uint32_t al[4][4];
#pragma unroll
                for (int mt = 0; mt < 4; mt++)
                    ldsm_x4(al[mt], base + TILE_B + swz(aR + mt * 16, aC + ks * 2));
#pragma unroll
                for (int mt = 0; mt < 4; mt++)
#pragma unroll
                    for (int nt = 0; nt < 4; nt++)
                        mma_f16(acc[mt][nt], al[mt], bq[nt]);
            }
        }
        __syncthreads();
    }

    // ---- epilogue ----
#pragma unroll
    for (int mt = 0; mt < 4; mt++) {
        int r0 = row0 + m0 + mt * 16 + g;
        int r1 = r0 + 8;
        if (EPI_TANH) {
#pragma unroll
            for (int nt = 0; nt < 4; nt++) {
                int cn = col0 + n0 + nt * 8 + t * 2;
                float bx = bias[cn], by = bias[cn + 1];
                if (r0 < Mm) {
                    uint32_t h, l;
                    split2h(tanhf(acc[mt][nt][0] + bx), tanhf(acc[mt][nt][1] + by), h, l);
                    outHi[((size_t)r0 * Nn + cn) >> 1] = h;
                    outLo[((size_t)r0 * Nn + cn) >> 1] = l;
                }
                if (r1 < Mm) {
                    uint32_t h, l;
                    split2h(tanhf(acc[mt][nt][2] + bx), tanhf(acc[mt][nt][3] + by), h, l);
                    outHi[((size_t)r1 * Nn + cn) >> 1] = h;
                    outLo[((size_t)r1 * Nn + cn) >> 1] = l;
                }
            }
        } else {
            float s0 = (r0 < Mm) ? dinv[r0] : 0.0f;
            float s1 = (r1 < Mm) ? dinv[r1] : 0.0f;
#pragma unroll
            for (int nt = 0; nt < 4; nt++) {
                int cn = col0 + n0 + nt * 8 + t * 2;
                if (r0 < Mm)
                    Ch[((size_t)r0 * Nn + cn) >> 1] = pack2h(acc[mt][nt][0] * s0, acc[mt][nt][1] * s0);
                if (r1 < Mm)
                    Ch[((size_t)r1 * Nn + cn) >> 1] = pack2h(acc[mt][nt][2] * s1, acc[mt][nt][3] * s1);
            }
        }
    }
}

// ---------------- aggregation over fp16 G: v = tanh/id( dinv[i]*(G[i] + sum G[src]) + b ) ----------------
template <int APPLY_TANH, int SPLIT_OUT>
__global__ void agg_kernel_t(const __half* __restrict__ G,
                             const float* __restrict__ bias,
                             const float* __restrict__ dinv,
                             const int* __restrict__ rowptr,
                             const int* __restrict__ colsrc,
                             float* __restrict__ outF,
                             uint2* __restrict__ outHi,
                             uint2* __restrict__ outLo,
                             int F4)
{
    int i = blockIdx.x;
    int t = threadIdx.x;
    const uint2* G4 = (const uint2*)G;   // 4 halves per uint2

    auto unpack_add = [](float4& a, uint2 v) {
        __half2 p0 = *reinterpret_cast<__half2*>(&v.x);
        __half2 p1 = *reinterpret_cast<__half2*>(&v.y);
        float2 f0 = __half22float2(p0);
        float2 f1 = __half22float2(p1);
        a.x += f0.x; a.y += f0.y; a.z += f1.x; a.w += f1.y;
    };

    float4 acc = make_float4(0.f, 0.f, 0.f, 0.f);
    unpack_add(acc, __ldg(&G4[(size_t)i * F4 + t]));

    int e   = rowptr[i];
    int end = rowptr[i + 1];
    for (; e + 4 <= end; e += 4) {
        int s0 = __ldg(&colsrc[e + 0]);
        int s1 = __ldg(&colsrc[e + 1]);
        int s2 = __ldg(&colsrc[e + 2]);
        int s3 = __ldg(&colsrc[e + 3]);
        uint2 v0 = __ldg(&G4[(size_t)s0 * F4 + t]);
        uint2 v1 = __ldg(&G4[(size_t)s1 * F4 + t]);
        uint2 v2 = __ldg(&G4[(size_t)s2 * F4 + t]);
        uint2 v3 = __ldg(&G4[(size_t)s3 * F4 + t]);
        unpack_add(acc, v0); unpack_add(acc, v1);
        unpack_add(acc, v2); unpack_add(acc, v3);
    }
    for (; e < end; ++e) {
        int s = __ldg(&colsrc[e]);
        unpack_add(acc, __ldg(&G4[(size_t)s * F4 + t]));
    }

    float di = dinv[i];
    float4 bb = ((const float4*)bias)[t];
    float4 r;
    r.x = fmaf(acc.x, di, bb.x);
    r.y = fmaf(acc.y, di, bb.y);
    r.z = fmaf(acc.z, di, bb.z);
    r.w = fmaf(acc.w, di, bb.w);
    if (APPLY_TANH) {
        r.x = tanhf(r.x); r.y = tanhf(r.y);
        r.z = tanhf(r.z); r.w = tanhf(r.w);
    }
    if (SPLIT_OUT) {
        uint32_t h0, l0, h1, l1;
        split2h(r.x, r.y, h0, l0);
        split2h(r.z, r.w, h1, l1);
        outHi[(size_t)i * F4 + t] = make_uint2(h0, h1);
        outLo[(size_t)i * F4 + t] = make_uint2(l0, l1);
    } else {
        ((float4*)outF)[(size_t)i * F4 + t] = r;
    }
}

// ---------------- launch ----------------
extern "C" void kernel_launch(void* const* d_in, const int* in_sizes, int n_in,
                              void* d_out, int out_size) {
    const float* x  = (const float*)d_in[0];
    const float* W1 = (const float*)d_in[1];
    const float* b1 = (const float*)d_in[2];
    const float* W2 = (const float*)d_in[3];
    const float* b2 = (const float*)d_in[4];
    const float* W3 = (const float*)d_in[5];
    const float* b3 = (const float*)d_in[6];
    const int*   ei = (const int*)d_in[7];    // int32 edge_index [2, E]
    float* out = (float*)d_out;

    const int N = N_NODES;
    const int E = in_sizes[7] / 2;

    float *dinv;
    int *cnt, *rowptr, *cursor, *colsrc;
    __half *bufH, *hiA, *loA, *hiB, *loB, *w1t, *w2t, *w3t;
    cudaGetSymbolAddress((void**)&bufH,   g_bufH);
    cudaGetSymbolAddress((void**)&dinv,   g_dinv);
    cudaGetSymbolAddress((void**)&cnt,    g_cnt);
    cudaGetSymbolAddress((void**)&rowptr, g_rowptr);
    cudaGetSymbolAddress((void**)&cursor, g_cursor);
    cudaGetSymbolAddress((void**)&colsrc, g_colsrc);
    cudaGetSymbolAddress((void**)&hiA,    g_hiA);
    cudaGetSymbolAddress((void**)&loA,    g_loA);
    cudaGetSymbolAddress((void**)&hiB,    g_hiB);
    cudaGetSymbolAddress((void**)&loB,    g_loB);
    cudaGetSymbolAddress((void**)&w1t,    g_W1t);
    cudaGetSymbolAddress((void**)&w2t,    g_W2t);
    cudaGetSymbolAddress((void**)&w3t,    g_W3t);

    static bool attr_set = false;
    if (!attr_set) {
        cudaFuncSetAttribute(gemm_mma_kernel<0>, cudaFuncAttributeMaxDynamicSharedMemorySize, GEMM_SMEM);
        cudaFuncSetAttribute(gemm_mma_kernel<1>, cudaFuncAttributeMaxDynamicSharedMemorySize, GEMM_SMEM);
        attr_set = true;
    }

    // --- fused one-shot prep (W fp16 transpose, cnt zero) ---
    fused_prep_kernel<<<(WTOT + N + 255) / 256, 256>>>(W1, W2, W3, w1t, w2t, w3t, cnt);
    // --- CSR by dst ---
    count_edges_kernel<<<(E / 2 + 255) / 256, 256>>>(ei, cnt, E);
    scan_kernel<<<1, 1024>>>(cnt, rowptr, cursor, dinv, N);
    fill_csr_kernel<<<(E / 2 + 255) / 256, 256>>>(ei, cursor, colsrc, E);

    const int MT = (N + 127) / 128;

    // --- layer 1: aggregate x first (256-wide), then GEMM with tanh+split epilogue ---
    agg_x_split_kernel<<<N, IN_DIM / 4>>>(x, dinv, rowptr, colsrc, (uint2*)hiA, (uint2*)loA);
    {
        dim3 grid(HID_DIM / 128, MT);
        gemm_mma_kernel<1><<<grid, 256, GEMM_SMEM>>>((uint32_t*)hiA, (uint32_t*)loA,
                                                     (uint32_t*)w1t, nullptr, b1,
                                                     nullptr, (uint32_t*)hiB, (uint32_t*)loB,
                                                     N, HID_DIM, IN_DIM);
    }
    // --- layer 2: GEMM (dinv epi, fp16 out) -> agg(tanh+split) ---
    {
        dim3 grid(HID_DIM / 128, MT);
        gemm_mma_kernel<0><<<grid, 256, GEMM_SMEM>>>((uint32_t*)hiB, (uint32_t*)loB,
                                                     (uint32_t*)w2t, dinv, nullptr,
                                                     (uint32_t*)bufH, nullptr, nullptr,
                                                     N, HID_DIM, HID_DIM);
        agg_kernel_t<1, 1><<<N, HID_DIM / 4>>>(bufH, b2, dinv, rowptr, colsrc,
                                               nullptr, (uint2*)hiA, (uint2*)loA, HID_DIM / 4);
    }
    // --- layer 3: GEMM (dinv epi, fp16 out, 256-wide) -> agg(bias, fp32 out) ---
    {
        dim3 grid(OUT_DIM / 128, MT);
        gemm_mma_kernel<0><<<grid, 256, GEMM_SMEM>>>((uint32_t*)hiA, (uint32_t*)loA,
                                                     (uint32_t*)w3t, dinv, nullptr,
                                                     (uint32_t*)bufH, nullptr, nullptr,
                                                     N, OUT_DIM, HID_DIM);
        agg_kernel_t<0, 0><<<N, OUT_DIM / 4>>>(bufH, b3, dinv, rowptr, colsrc,
                                               out, nullptr, nullptr, OUT_DIM / 4);
    }
}

// round 11
// speedup vs baseline: 3.6264x; 1.2674x over previous
#include <cuda_runtime.h>
#include <cuda_fp16.h>
#include <math.h>
#include <stdint.h>

// ---------------- problem constants ----------------
#define N_NODES 10000
#define N_EDGES 160000
#define IN_DIM  256
#define HID_DIM 512
#define OUT_DIM 256

// ---------------- device scratch (no allocs allowed) ----------------
__device__ __half g_bufH[N_NODES * HID_DIM];     // GEMM fp16 output (scaled)
__device__ __half g_hiA[N_NODES * HID_DIM];      // fp16 activation buffer A
__device__ __half g_hiB[N_NODES * HID_DIM];      // fp16 activation buffer B
__device__ __half g_W1t[IN_DIM * HID_DIM];       // W^T fp16
__device__ __half g_W2t[HID_DIM * HID_DIM];
__device__ __half g_W3t[HID_DIM * OUT_DIM];
__device__ float  g_dinv[N_NODES];
__device__ int    g_cnt[N_NODES];
__device__ int    g_rowptr[N_NODES + 1];
__device__ int    g_cursor[N_NODES];
__device__ int    g_colsrc[N_EDGES];

__device__ __forceinline__ uint32_t pack2h(float a, float b) {
    __half2 h = __floats2half2_rn(a, b);
    return *reinterpret_cast<uint32_t*>(&h);
}

// ---------------- fused one-shot prep: W1/W2/W3 -> W^T fp16, cnt zero ----------------
#define WTOT (IN_DIM * HID_DIM + HID_DIM * HID_DIM + HID_DIM * OUT_DIM)   // 524288
__global__ void fused_prep_kernel(const float* __restrict__ W1, const float* __restrict__ W2,
                                  const float* __restrict__ W3,
                                  __half* __restrict__ w1t, __half* __restrict__ w2t,
                                  __half* __restrict__ w3t,
                                  int* __restrict__ cnt) {
    const int S1 = IN_DIM * HID_DIM;
    const int S2 = S1 + HID_DIM * HID_DIM;
    int i = blockIdx.x * blockDim.x + threadIdx.x;
    if (i < WTOT) {
        if (i < S1) {
            int k = i / HID_DIM, n = i % HID_DIM;
            w1t[(size_t)n * IN_DIM + k] = __float2half_rn(W1[i]);
        } else if (i < S2) {
            int j = i - S1;
            int k = j / HID_DIM, n = j % HID_DIM;
            w2t[(size_t)n * HID_DIM + k] = __float2half_rn(W2[j]);
        } else {
            int j = i - S2;
            int k = j / OUT_DIM, n = j % OUT_DIM;
            w3t[(size_t)n * HID_DIM + k] = __float2half_rn(W3[j]);
        }
    } else if (i < WTOT + N_NODES) {
        cnt[i - WTOT] = 0;
    }
}

// ---------------- preprocessing kernels (2 edges/thread) ----------------
__global__ void count_edges_kernel(const int* __restrict__ ei, int* cnt, int E) {
    int e = (blockIdx.x * blockDim.x + threadIdx.x) * 2;
    if (e < E) {
        int d = ei[E + e];
        if (d >= 0 && d < N_NODES) atomicAdd(&cnt[d], 1);
    }
    if (e + 1 < E) {
        int d = ei[E + e + 1];
        if (d >= 0 && d < N_NODES) atomicAdd(&cnt[d], 1);
    }
}

__global__ void scan_kernel(const int* __restrict__ cnt, int* rowptr, int* cursor,
                            float* dinv, int n) {
    __shared__ int ssum[1024];
    int tid = threadIdx.x;
    const int CH = (n + 1023) / 1024;
    int base = tid * CH;
    int local = 0;
    for (int i = 0; i < CH; i++) {
        int idx = base + i;
        if (idx < n) local += cnt[idx];
    }
    ssum[tid] = local;
    __syncthreads();
    for (int off = 1; off < 1024; off <<= 1) {
        int v = ssum[tid];
        int add = (tid >= off) ? ssum[tid - off] : 0;
        __syncthreads();
        ssum[tid] = v + add;
        __syncthreads();
    }
    int run = (tid > 0) ? ssum[tid - 1] : 0;
    for (int i = 0; i < CH; i++) {
        int idx = base + i;
        if (idx < n) {
            rowptr[idx] = run;
            cursor[idx] = run;
            int c = cnt[idx];
            run += c;
            dinv[idx] = rsqrtf((float)c + 1.0f);
        }
    }
    if (tid == 1023) rowptr[n] = run;
}

__global__ void fill_csr_kernel(const int* __restrict__ ei, int* cursor,
                                int* colsrc, int E) {
    int e = (blockIdx.x * blockDim.x + threadIdx.x) * 2;
    if (e < E) {
        int s = ei[e];
        int d = ei[E + e];
        if (d >= 0 && d < N_NODES) {
            int p = atomicAdd(&cursor[d], 1);
            colsrc[p] = s;
        }
    }
    if (e + 1 < E) {
        int s = ei[e + 1];
        int d = ei[E + e + 1];
        if (d >= 0 && d < N_NODES) {
            int p = atomicAdd(&cursor[d], 1);
            colsrc[p] = s;
        }
    }
}

// ---------------- layer-1 pre-aggregation on raw x (256-wide gather) -> fp16 ----------------
__global__ void agg_x_kernel(const float* __restrict__ X,
                             const float* __restrict__ dinv,
                             const int* __restrict__ rowptr,
                             const int* __restrict__ colsrc,
                             uint2* __restrict__ outH)
{
    const int F4 = IN_DIM / 4;   // 64
    int i = blockIdx.x;
    int t = threadIdx.x;
    const float4* X4 = (const float4*)X;

    float di = dinv[i];
    float4 xv = __ldg(&X4[(size_t)i * F4 + t]);
    float4 acc;
    acc.x = xv.x * di; acc.y = xv.y * di; acc.z = xv.z * di; acc.w = xv.w * di;

    int e   = rowptr[i];
    int end = rowptr[i + 1];
    for (; e + 2 <= end; e += 2) {
        int s0 = __ldg(&colsrc[e + 0]);
        int s1 = __ldg(&colsrc[e + 1]);
        float w0 = __ldg(&dinv[s0]);
        float w1 = __ldg(&dinv[s1]);
        float4 v0 = __ldg(&X4[(size_t)s0 * F4 + t]);
        float4 v1 = __ldg(&X4[(size_t)s1 * F4 + t]);
        acc.x += v0.x * w0 + v1.x * w1;
        acc.y += v0.y * w0 + v1.y * w1;
        acc.z += v0.z * w0 + v1.z * w1;
        acc.w += v0.w * w0 + v1.w * w1;
    }
    for (; e < end; ++e) {
        int s = __ldg(&colsrc[e]);
        float w = __ldg(&dinv[s]);
        float4 v = __ldg(&X4[(size_t)s * F4 + t]);
        acc.x += v.x * w; acc.y += v.y * w; acc.z += v.z * w; acc.w += v.w * w;
    }

    outH[(size_t)i * F4 + t] = make_uint2(pack2h(acc.x * di, acc.y * di),
                                          pack2h(acc.z * di, acc.w * di));
}

// ---------------- mma.sync fp16 GEMM (single operand pass), 2 CTAs/SM ----------------
// EPI_TANH=0: Ch[r][c] = half( dinv[r] * acc )
// EPI_TANH=1: Ch[r][c] = half( tanh(acc + bias[c]) )
#define TILE_B 8192
#define STAGE_B (2 * TILE_B)       // 16384
#define GEMM_SMEM (2 * STAGE_B)    // 32768

__device__ __forceinline__ uint32_t swz(uint32_t row, uint32_t c) {
    return ((row >> 1) << 7) | ((((((row & 1u) << 2) | c)) ^ ((row >> 1) & 3u)) << 4);
}
__device__ __forceinline__ void cp16(uint32_t dst, const void* src, bool pred) {
    int sz = pred ? 16 : 0;
    asm volatile("cp.async.cg.shared.global [%0], [%1], 16, %2;"
                 :: "r"(dst), "l"(src), "r"(sz) : "memory");
}
__device__ __forceinline__ void mma_f16(float c[4], const uint32_t a[4], const uint32_t b[2]) {
    asm volatile(
        "mma.sync.aligned.m16n8k16.row.col.f32.f16.f16.f32 "
        "{%0,%1,%2,%3}, {%4,%5,%6,%7}, {%8,%9}, {%0,%1,%2,%3};"
        : "+f"(c[0]), "+f"(c[1]), "+f"(c[2]), "+f"(c[3])
        : "r"(a[0]), "r"(a[1]), "r"(a[2]), "r"(a[3]), "r"(b[0]), "r"(b[1]));
}
__device__ __forceinline__ void ldsm_x4(uint32_t r[4], uint32_t addr) {
    asm volatile("ldmatrix.sync.aligned.m8n8.x4.shared.b16 {%0,%1,%2,%3}, [%4];"
                 : "=r"(r[0]), "=r"(r[1]), "=r"(r[2]), "=r"(r[3]) : "r"(addr));
}
__device__ __forceinline__ void ldsm_x2(uint32_t r[2], uint32_t addr) {
    asm volatile("ldmatrix.sync.aligned.m8n8.x2.shared.b16 {%0,%1}, [%2];"
                 : "=r"(r[0]), "=r"(r[1]) : "r"(addr));
}
__device__ __forceinline__ uint32_t smem_u32p(const void* p) {
    uint32_t a;
    asm("{ .reg .u64 t; cvta.to.shared.u64 t, %1; cvt.u32.u64 %0, t; }" : "=r"(a) : "l"(p));
    return a;
}

template <int EPI_TANH>
__global__ __launch_bounds__(256, 2) void gemm_mma_kernel(
    const uint32_t* __restrict__ A2, const uint32_t* __restrict__ B2,
    const float* __restrict__ dinv, const float* __restrict__ bias,
    uint32_t* __restrict__ Ch,
    int Mm, int Nn, int Kk)
{
    extern __shared__ __align__(16) uint32_t sm[];
    const uint32_t sb = smem_u32p(sm);

    const int tid = threadIdx.x;
    const int wid = tid >> 5;
    const int lid = tid & 31;
    const int g = lid >> 2;
    const int t = lid & 3;
    const int row0 = blockIdx.y * 128;
    const int col0 = blockIdx.x * 128;
    const int m0 = (wid & 1) * 64;
    const int n0 = (wid >> 1) * 32;
    const int Ku = Kk >> 1;

    float acc[4][4][4];
#pragma unroll
    for (int mt = 0; mt < 4; mt++)
#pragma unroll
        for (int nt = 0; nt < 4; nt++)
#pragma unroll
            for (int i = 0; i < 4; i++) acc[mt][nt][i] = 0.0f;

    // loader: 2 tiles x 128 rows x 4 chunks = 1024 chunks, 256 threads -> 4 iters
    auto load_tiles = [&](int buf, int kt) {
        const int k0u = kt * 16;
#pragma unroll
        for (int it = 0; it < 4; it++) {
            int c = it * 256 + tid;
            int tile = c >> 9;
            int r = (c >> 2) & 127;
            int ch = c & 3;
            uint32_t dst = sb + (uint32_t)(buf * STAGE_B + tile * TILE_B) + swz((uint32_t)r, (uint32_t)ch);
            const uint32_t* src;
            bool p = true;
            if (tile == 0) {
                int gr = row0 + r;
                p = gr < Mm;
                int gra = p ? gr : 0;
                src = A2 + (size_t)gra * Ku + k0u + ch * 4;
            } else {
                int gn = col0 + r;
                src = B2 + (size_t)gn * Ku + k0u + ch * 4;
            }
            cp16(dst, src, p);
        }
        asm volatile("cp.async.commit_group;" ::: "memory");
    };

    const int nkt = Kk / 32;
    load_tiles(0, 0);

    const uint32_t aR = (uint32_t)(m0 + (lid & 15));
    const uint32_t aC = (uint32_t)(lid >> 4);
    const uint32_t bR = (uint32_t)(n0 + (lid & 7));
    const uint32_t bC = (uint32_t)((lid >> 3) & 1);

    for (int kt = 0; kt < nkt; kt++) {
        int buf = kt & 1;
        if (kt + 1 < nkt) {
            load_tiles(buf ^ 1, kt + 1);
            asm volatile("cp.async.wait_group 1;" ::: "memory");
        } else {
            asm volatile("cp.async.wait_group 0;" ::: "memory");
        }
        __syncthreads();

        const uint32_t base = sb + (uint32_t)(buf * STAGE_B);

#pragma unroll
        for (int ks = 0; ks < 2; ks++) {
            uint32_t ah[4][4];
            uint32_t bq[4][2];
#pragma unroll
            for (int mt = 0; mt < 4; mt++)
                ldsm_x4(ah[mt], base + swz(aR + mt * 16, aC + ks * 2));
#pragma unroll
            for (int nt = 0; nt < 4; nt++)
                ldsm_x2(bq[nt], base + TILE_B + swz(bR + nt * 8, bC + ks * 2));

#pragma unroll
            for (int mt = 0; mt < 4; mt++)
#pragma unroll
                for (int nt = 0; nt < 4; nt++)
                    mma_f16(acc[mt][nt], ah[mt], bq[nt]);
        }
        __syncthreads();
    }

    // ---- epilogue (packed half2 out) ----
#pragma unroll
    for (int mt = 0; mt < 4; mt++) {
        int r0 = row0 + m0 + mt * 16 + g;
        int r1 = r0 + 8;
        if (EPI_TANH) {
#pragma unroll
            for (int nt = 0; nt < 4; nt++) {
                int cn = col0 + n0 + nt * 8 + t * 2;
                float bx = bias[cn], by = bias[cn + 1];
                if (r0 < Mm)
                    Ch[((size_t)r0 * Nn + cn) >> 1] =
                        pack2h(tanhf(acc[mt][nt][0] + bx), tanhf(acc[mt][nt][1] + by));
                if (r1 < Mm)
                    Ch[((size_t)r1 * Nn + cn) >> 1] =
                        pack2h(tanhf(acc[mt][nt][2] + bx), tanhf(acc[mt][nt][3] + by));
            }
        } else {
            float s0 = (r0 < Mm) ? dinv[r0] : 0.0f;
            float s1 = (r1 < Mm) ? dinv[r1] : 0.0f;
#pragma unroll
            for (int nt = 0; nt < 4; nt++) {
                int cn = col0 + n0 + nt * 8 + t * 2;
                if (r0 < Mm)
                    Ch[((size_t)r0 * Nn + cn) >> 1] = pack2h(acc[mt][nt][0] * s0, acc[mt][nt][1] * s0);
                if (r1 < Mm)
                    Ch[((size_t)r1 * Nn + cn) >> 1] = pack2h(acc[mt][nt][2] * s1, acc[mt][nt][3] * s1);
            }
        }
    }
}

// ---------------- aggregation over fp16 G: v = tanh/id( dinv[i]*(G[i] + sum G[src]) + b ) ----------------
// FP16_OUT=1 -> packed fp16 (GEMM input), else fp32 out
template <int APPLY_TANH, int FP16_OUT>
__global__ void agg_kernel_t(const __half* __restrict__ G,
                             const float* __restrict__ bias,
                             const float* __restrict__ dinv,
                             const int* __restrict__ rowptr,
                             const int* __restrict__ colsrc,
                             float* __restrict__ outF,
                             uint2* __restrict__ outH,
                             int F4)
{
    int i = blockIdx.x;
    int t = threadIdx.x;
    const uint2* G4 = (const uint2*)G;   // 4 halves per uint2

    auto unpack_add = [](float4& a, uint2 v) {
        __half2 p0 = *reinterpret_cast<__half2*>(&v.x);
        __half2 p1 = *reinterpret_cast<__half2*>(&v.y);
        float2 f0 = __half22float2(p0);
        float2 f1 = __half22float2(p1);
        a.x += f0.x; a.y += f0.y; a.z += f1.x; a.w += f1.y;
    };

    float4 acc = make_float4(0.f, 0.f, 0.f, 0.f);
    unpack_add(acc, __ldg(&G4[(size_t)i * F4 + t]));

    int e   = rowptr[i];
    int end = rowptr[i + 1];
    for (; e + 4 <= end; e += 4) {
        int s0 = __ldg(&colsrc[e + 0]);
        int s1 = __ldg(&colsrc[e + 1]);
        int s2 = __ldg(&colsrc[e + 2]);
        int s3 = __ldg(&colsrc[e + 3]);
        uint2 v0 = __ldg(&G4[(size_t)s0 * F4 + t]);
        uint2 v1 = __ldg(&G4[(size_t)s1 * F4 + t]);
        uint2 v2 = __ldg(&G4[(size_t)s2 * F4 + t]);
        uint2 v3 = __ldg(&G4[(size_t)s3 * F4 + t]);
        unpack_add(acc, v0); unpack_add(acc, v1);
        unpack_add(acc, v2); unpack_add(acc, v3);
    }
    for (; e < end; ++e) {
        int s = __ldg(&colsrc[e]);
        unpack_add(acc, __ldg(&G4[(size_t)s * F4 + t]));
    }

    float di = dinv[i];
    float4 bb = ((const float4*)bias)[t];
    float4 r;
    r.x = fmaf(acc.x, di, bb.x);
    r.y = fmaf(acc.y, di, bb.y);
    r.z = fmaf(acc.z, di, bb.z);
    r.w = fmaf(acc.w, di, bb.w);
    if (APPLY_TANH) {
        r.x = tanhf(r.x); r.y = tanhf(r.y);
        r.z = tanhf(r.z); r.w = tanhf(r.w);
    }
    if (FP16_OUT) {
        outH[(size_t)i * F4 + t] = make_uint2(pack2h(r.x, r.y), pack2h(r.z, r.w));
    } else {
        ((float4*)outF)[(size_t)i * F4 + t] = r;
    }
}

// ---------------- launch ----------------
extern "C" void kernel_launch(void* const* d_in, const int* in_sizes, int n_in,
                              void* d_out, int out_size) {
    const float* x  = (const float*)d_in[0];
    const float* W1 = (const float*)d_in[1];
    const float* b1 = (const float*)d_in[2];
    const float* W2 = (const float*)d_in[3];
    const float* b2 = (const float*)d_in[4];
    const float* W3 = (const float*)d_in[5];
    const float* b3 = (const float*)d_in[6];
    const int*   ei = (const int*)d_in[7];    // int32 edge_index [2, E]
    float* out = (float*)d_out;

    const int N = N_NODES;
    const int E = in_sizes[7] / 2;

    float *dinv;
    int *cnt, *rowptr, *cursor, *colsrc;
    __half *bufH, *hiA, *hiB, *w1t, *w2t, *w3t;
    cudaGetSymbolAddress((void**)&bufH,   g_bufH);
    cudaGetSymbolAddress((void**)&dinv,   g_dinv);
    cudaGetSymbolAddress((void**)&cnt,    g_cnt);
    cudaGetSymbolAddress((void**)&rowptr, g_rowptr);
    cudaGetSymbolAddress((void**)&cursor, g_cursor);
    cudaGetSymbolAddress((void**)&colsrc, g_colsrc);
    cudaGetSymbolAddress((void**)&hiA,    g_hiA);
    cudaGetSymbolAddress((void**)&hiB,    g_hiB);
    cudaGetSymbolAddress((void**)&w1t,    g_W1t);
    cudaGetSymbolAddress((void**)&w2t,    g_W2t);
    cudaGetSymbolAddress((void**)&w3t,    g_W3t);

    static bool attr_set = false;
    if (!attr_set) {
        cudaFuncSetAttribute(gemm_mma_kernel<0>, cudaFuncAttributeMaxDynamicSharedMemorySize, GEMM_SMEM);
        cudaFuncSetAttribute(gemm_mma_kernel<1>, cudaFuncAttributeMaxDynamicSharedMemorySize, GEMM_SMEM);
        attr_set = true;
    }

    // --- fused one-shot prep (W fp16 transpose, cnt zero) ---
    fused_prep_kernel<<<(WTOT + N + 255) / 256, 256>>>(W1, W2, W3, w1t, w2t, w3t, cnt);
    // --- CSR by dst ---
    count_edges_kernel<<<(E / 2 + 255) / 256, 256>>>(ei, cnt, E);
    scan_kernel<<<1, 1024>>>(cnt, rowptr, cursor, dinv, N);
    fill_csr_kernel<<<(E / 2 + 255) / 256, 256>>>(ei, cursor, colsrc, E);

    const int MT = (N + 127) / 128;

    // --- layer 1: aggregate x (256-wide) -> fp16, then GEMM with tanh epilogue ---
    agg_x_kernel<<<N, IN_DIM / 4>>>(x, dinv, rowptr, colsrc, (uint2*)hiA);
    {
        dim3 grid(HID_DIM / 128, MT);
        gemm_mma_kernel<1><<<grid, 256, GEMM_SMEM>>>((uint32_t*)hiA, (uint32_t*)w1t,
                                                     nullptr, b1, (uint32_t*)hiB,
                                                     N, HID_DIM, IN_DIM);
    }
    // --- layer 2: GEMM (dinv epi, fp16 out) -> agg(tanh, fp16 out) ---
    {
        dim3 grid(HID_DIM / 128, MT);
        gemm_mma_kernel<0><<<grid, 256, GEMM_SMEM>>>((uint32_t*)hiB, (uint32_t*)w2t,
                                                     dinv, nullptr, (uint32_t*)bufH,
                                                     N, HID_DIM, HID_DIM);
        agg_kernel_t<1, 1><<<N, HID_DIM / 4>>>(bufH, b2, dinv, rowptr, colsrc,
                                               nullptr, (uint2*)hiA, HID_DIM / 4);
    }
    // --- layer 3: GEMM (dinv epi, fp16 out) -> agg(bias, fp32 out) ---
    {
        dim3 grid(OUT_DIM / 128, MT);
        gemm_mma_kernel<0><<<grid, 256, GEMM_SMEM>>>((uint32_t*)hiA, (uint32_t*)w3t,
                                                     dinv, nullptr, (uint32_t*)bufH,
                                                     N, OUT_DIM, HID_DIM);
        agg_kernel_t<0, 0><<<N, OUT_DIM / 4>>>(bufH, b3, dinv, rowptr, colsrc,
                                               out, nullptr, OUT_DIM / 4);
    }
}